// round 1
// baseline (speedup 1.0000x reference)
#include <cuda_runtime.h>
#include <math.h>

#define NHEADS 8
#define DH     64
#define BATCH  4
#define NQS    1024
#define NKS    2048
#define DM     512

// Scratch in device globals (no allocation allowed in kernel_launch).
__device__ float g_Q [(size_t)BATCH * NQS * DM];
__device__ float g_K [(size_t)BATCH * NKS * DM];
__device__ float g_V [(size_t)BATCH * NKS * DM];
__device__ float g_AO[(size_t)BATCH * NQS * DM];

// ---------------------------------------------------------------------------
// SGEMM: C[M,N] = A[M,K] @ W[N,K]^T (+ bias[N]).  Both A and W row-major with
// K contiguous ("NT" gemm). 128x128 tile, BK=8, 256 threads, 8x8 per thread.
// ---------------------------------------------------------------------------
__device__ __forceinline__ void gemm_nt_body(
    const float* __restrict__ A, const float* __restrict__ W,
    const float* __restrict__ bias, float* __restrict__ C,
    int M, int N, int K, bool addBias)
{
    __shared__ float As[8 * 132];
    __shared__ float Bs[8 * 132];

    const int tid = threadIdx.x;
    const int ty  = tid >> 4;        // 0..15
    const int tx  = tid & 15;        // 0..15
    const int m0  = blockIdx.y * 128;
    const int n0  = blockIdx.x * 128;

    const int lRow = tid >> 1;           // 0..127
    const int lCol = (tid & 1) << 2;     // 0 or 4

    const float* Ap = A + (size_t)(m0 + lRow) * K + lCol;
    const float* Wp = W + (size_t)(n0 + lRow) * K + lCol;

    float acc[8][8];
    #pragma unroll
    for (int i = 0; i < 8; i++)
        #pragma unroll
        for (int j = 0; j < 8; j++) acc[i][j] = 0.f;

    for (int k0 = 0; k0 < K; k0 += 8) {
        float4 av = *(const float4*)(Ap + k0);
        float4 wv = *(const float4*)(Wp + k0);
        As[(lCol + 0) * 132 + lRow] = av.x;
        As[(lCol + 1) * 132 + lRow] = av.y;
        As[(lCol + 2) * 132 + lRow] = av.z;
        As[(lCol + 3) * 132 + lRow] = av.w;
        Bs[(lCol + 0) * 132 + lRow] = wv.x;
        Bs[(lCol + 1) * 132 + lRow] = wv.y;
        Bs[(lCol + 2) * 132 + lRow] = wv.z;
        Bs[(lCol + 3) * 132 + lRow] = wv.w;
        __syncthreads();

        #pragma unroll
        for (int kk = 0; kk < 8; kk++) {
            float4 a0 = *(const float4*)&As[kk * 132 + ty * 8];
            float4 a1 = *(const float4*)&As[kk * 132 + ty * 8 + 4];
            float4 b0 = *(const float4*)&Bs[kk * 132 + tx * 8];
            float4 b1 = *(const float4*)&Bs[kk * 132 + tx * 8 + 4];
            float a[8] = {a0.x, a0.y, a0.z, a0.w, a1.x, a1.y, a1.z, a1.w};
            float b[8] = {b0.x, b0.y, b0.z, b0.w, b1.x, b1.y, b1.z, b1.w};
            #pragma unroll
            for (int i = 0; i < 8; i++)
                #pragma unroll
                for (int j = 0; j < 8; j++)
                    acc[i][j] = fmaf(a[i], b[j], acc[i][j]);
        }
        __syncthreads();
    }

    #pragma unroll
    for (int i = 0; i < 8; i++) {
        float* cp = C + (size_t)(m0 + ty * 8 + i) * N + n0 + tx * 8;
        float4 r0 = make_float4(acc[i][0], acc[i][1], acc[i][2], acc[i][3]);
        float4 r1 = make_float4(acc[i][4], acc[i][5], acc[i][6], acc[i][7]);
        if (addBias) {
            const float* bp = bias + n0 + tx * 8;
            r0.x += bp[0]; r0.y += bp[1]; r0.z += bp[2]; r0.w += bp[3];
            r1.x += bp[4]; r1.y += bp[5]; r1.z += bp[6]; r1.w += bp[7];
        }
        *(float4*)cp       = r0;
        *(float4*)(cp + 4) = r1;
    }
}

__global__ __launch_bounds__(256) void gemm_q_kernel(const float* __restrict__ A,
                                                     const float* __restrict__ W) {
    gemm_nt_body(A, W, nullptr, g_Q, BATCH * NQS, DM, DM, false);
}
__global__ __launch_bounds__(256) void gemm_k_kernel(const float* __restrict__ A,
                                                     const float* __restrict__ W) {
    gemm_nt_body(A, W, nullptr, g_K, BATCH * NKS, DM, DM, false);
}
__global__ __launch_bounds__(256) void gemm_v_kernel(const float* __restrict__ A,
                                                     const float* __restrict__ W) {
    gemm_nt_body(A, W, nullptr, g_V, BATCH * NKS, DM, DM, false);
}
__global__ __launch_bounds__(256) void gemm_o_kernel(const float* __restrict__ W,
                                                     const float* __restrict__ bo,
                                                     float* __restrict__ out) {
    gemm_nt_body(g_AO, W, bo, out, BATCH * NQS, DM, DM, true);
}

// ---------------------------------------------------------------------------
// Flash attention with additive bias.
//   Per CTA: one (batch, head, 64-row Q tile). Loop over 64-wide K/V tiles.
//   scores = (Q K^T) * scale + bias[b, q, k]; online softmax; O += P V.
// smem (dynamic): Qs[64][68] (d-major), Ks[64][68] (d-major),
//                 Vs[64][64] (k-major), Ps[64][68].
// Threads: 256 = 16x16; each thread owns a 4(q) x 4 tile.
// ---------------------------------------------------------------------------
#define ATTN_SMEM ((2 * 64 * 68 + 64 * 64 + 64 * 68) * 4)

__global__ __launch_bounds__(256) void attn_kernel(const float* __restrict__ bias)
{
    extern __shared__ float sm[];
    float* Qs = sm;                           // 64*68
    float* Ks = sm + 64 * 68;                 // 64*68
    float* Vs = sm + 2 * 64 * 68;             // 64*64
    float* Ps = sm + 2 * 64 * 68 + 64 * 64;   // 64*68

    const int tid = threadIdx.x;
    const int ty  = tid >> 4;    // 0..15 -> q rows 4*ty..4*ty+3
    const int tx  = tid & 15;    // 0..15 -> cols 4*tx..4*tx+3
    const int q0  = blockIdx.x * 64;
    const int h   = blockIdx.y;
    const int b   = blockIdx.z;

    // Load Q tile transposed: Qs[d][m]
    const float* Qg = g_Q + ((size_t)b * NQS + q0) * DM + h * DH;
    #pragma unroll
    for (int i = 0; i < 16; i++) {
        int idx = tid + 256 * i;
        int m = idx >> 6, d = idx & 63;
        Qs[d * 68 + m] = Qg[(size_t)m * DM + d];
    }

    float o[4][4];
    #pragma unroll
    for (int i = 0; i < 4; i++)
        #pragma unroll
        for (int j = 0; j < 4; j++) o[i][j] = 0.f;
    float mr[4] = {-1e30f, -1e30f, -1e30f, -1e30f};
    float lr[4] = {0.f, 0.f, 0.f, 0.f};

    const float* biasRow = bias + ((size_t)b * NQS + q0 + 4 * ty) * NKS;

    for (int kb = 0; kb < NKS / 64; kb++) {
        const int k0 = kb * 64;
        const float* Kg = g_K + ((size_t)b * NKS + k0) * DM + h * DH;
        const float* Vg = g_V + ((size_t)b * NKS + k0) * DM + h * DH;

        __syncthreads();   // previous iteration's PV reads done
        #pragma unroll
        for (int i = 0; i < 16; i++) {
            int idx = tid + 256 * i;
            int r = idx >> 6, d = idx & 63;
            Ks[d * 68 + r]  = Kg[(size_t)r * DM + d];
            Vs[r * 64 + d]  = Vg[(size_t)r * DM + d];
        }
        __syncthreads();

        // S = Q K^T (64x64 tile, per thread 4x4)
        float s[4][4];
        #pragma unroll
        for (int i = 0; i < 4; i++)
            #pragma unroll
            for (int j = 0; j < 4; j++) s[i][j] = 0.f;

        #pragma unroll 16
        for (int dd = 0; dd < 64; dd++) {
            float4 q = *(const float4*)&Qs[dd * 68 + 4 * ty];
            float4 k = *(const float4*)&Ks[dd * 68 + 4 * tx];
            float qa[4] = {q.x, q.y, q.z, q.w};
            float ka[4] = {k.x, k.y, k.z, k.w};
            #pragma unroll
            for (int i = 0; i < 4; i++)
                #pragma unroll
                for (int j = 0; j < 4; j++)
                    s[i][j] = fmaf(qa[i], ka[j], s[i][j]);
        }

        // scale + bias, online softmax per row
        #pragma unroll
        for (int i = 0; i < 4; i++) {
            float4 bv = *(const float4*)&biasRow[(size_t)i * NKS + k0 + 4 * tx];
            s[i][0] = fmaf(s[i][0], 0.125f, bv.x);
            s[i][1] = fmaf(s[i][1], 0.125f, bv.y);
            s[i][2] = fmaf(s[i][2], 0.125f, bv.z);
            s[i][3] = fmaf(s[i][3], 0.125f, bv.w);

            float rm = fmaxf(fmaxf(s[i][0], s[i][1]), fmaxf(s[i][2], s[i][3]));
            rm = fmaxf(rm, __shfl_xor_sync(0xffffffffu, rm, 1));
            rm = fmaxf(rm, __shfl_xor_sync(0xffffffffu, rm, 2));
            rm = fmaxf(rm, __shfl_xor_sync(0xffffffffu, rm, 4));
            rm = fmaxf(rm, __shfl_xor_sync(0xffffffffu, rm, 8));

            float mnew = fmaxf(mr[i], rm);
            float corr = __expf(mr[i] - mnew);
            mr[i] = mnew;

            float p0 = __expf(s[i][0] - mnew);
            float p1 = __expf(s[i][1] - mnew);
            float p2 = __expf(s[i][2] - mnew);
            float p3 = __expf(s[i][3] - mnew);
            float rs = p0 + p1 + p2 + p3;
            rs += __shfl_xor_sync(0xffffffffu, rs, 1);
            rs += __shfl_xor_sync(0xffffffffu, rs, 2);
            rs += __shfl_xor_sync(0xffffffffu, rs, 4);
            rs += __shfl_xor_sync(0xffffffffu, rs, 8);
            lr[i] = lr[i] * corr + rs;

            o[i][0] *= corr; o[i][1] *= corr; o[i][2] *= corr; o[i][3] *= corr;

            *(float4*)&Ps[(4 * ty + i) * 68 + 4 * tx] = make_float4(p0, p1, p2, p3);
        }
        __syncthreads();

        // O += P V  (P: 64x64 in smem, V: k-major in smem)
        #pragma unroll 16
        for (int kk = 0; kk < 64; kk++) {
            float4 v = *(const float4*)&Vs[kk * 64 + 4 * tx];
            #pragma unroll
            for (int i = 0; i < 4; i++) {
                float pr = Ps[(4 * ty + i) * 68 + kk];
                o[i][0] = fmaf(pr, v.x, o[i][0]);
                o[i][1] = fmaf(pr, v.y, o[i][1]);
                o[i][2] = fmaf(pr, v.z, o[i][2]);
                o[i][3] = fmaf(pr, v.w, o[i][3]);
            }
        }
    }

    // normalize and store to attention output buffer (B, Nq, H*Dh)
    float* Og = g_AO + ((size_t)b * NQS + q0 + 4 * ty) * DM + h * DH + 4 * tx;
    #pragma unroll
    for (int i = 0; i < 4; i++) {
        float inv = 1.f / lr[i];
        *(float4*)(Og + (size_t)i * DM) =
            make_float4(o[i][0] * inv, o[i][1] * inv, o[i][2] * inv, o[i][3] * inv);
    }
}

// ---------------------------------------------------------------------------
// Launch
// ---------------------------------------------------------------------------
extern "C" void kernel_launch(void* const* d_in, const int* in_sizes, int n_in,
                              void* d_out, int out_size)
{
    const float* x    = (const float*)d_in[0];  // (4,1024,512)
    const float* ctx  = (const float*)d_in[1];  // (4,2048,512)
    const float* bias = (const float*)d_in[2];  // (4,1024,2048)
    const float* Wq   = (const float*)d_in[3];  // (512,512)
    const float* Wk   = (const float*)d_in[4];
    const float* Wv   = (const float*)d_in[5];
    const float* Wo   = (const float*)d_in[6];
    const float* bo   = (const float*)d_in[7];  // (512,)
    float* out = (float*)d_out;                 // (4,1024,512)

    cudaFuncSetAttribute(attn_kernel,
                         cudaFuncAttributeMaxDynamicSharedMemorySize, ATTN_SMEM);

    dim3 blk(256);
    gemm_q_kernel<<<dim3(DM / 128, (BATCH * NQS) / 128), blk>>>(x, Wq);
    gemm_k_kernel<<<dim3(DM / 128, (BATCH * NKS) / 128), blk>>>(ctx, Wk);
    gemm_v_kernel<<<dim3(DM / 128, (BATCH * NKS) / 128), blk>>>(ctx, Wv);
    attn_kernel<<<dim3(NQS / 64, NHEADS, BATCH), blk, ATTN_SMEM>>>(bias);
    gemm_o_kernel<<<dim3(DM / 128, (BATCH * NQS) / 128), blk>>>(Wo, bo, out);
}

// round 3
// speedup vs baseline: 2.8946x; 2.8946x over previous
#include <cuda_runtime.h>
#include <cstdint>
#include <math.h>

#define NHEADS 8
#define DH     64
#define BATCH  4
#define NQS    1024
#define NKS    2048
#define DM     512

// Scratch in device globals (no allocation allowed in kernel_launch).
__device__ float g_Q [(size_t)BATCH * NQS * DM];
__device__ float g_K [(size_t)BATCH * NKS * DM];
__device__ float g_V [(size_t)BATCH * NKS * DM];
__device__ float g_AO[(size_t)BATCH * NQS * DM];

// ===========================================================================
// Helpers: tf32 mma.sync (sm_80 baseline PTX -> works on plain sm_103 target)
// ===========================================================================
__device__ __forceinline__ uint32_t smem_u32(const void* p) {
    uint32_t a;
    asm("{ .reg .u64 t; cvta.to.shared.u64 t, %1; cvt.u32.u64 %0, t; }"
        : "=r"(a) : "l"(p));
    return a;
}
__device__ __forceinline__ uint32_t f2tf32(float f) {
    uint32_t u;
    asm("cvt.rna.tf32.f32 %0, %1;" : "=r"(u) : "f"(f));
    return u;
}
// D += A(16x8) * B(8x8), tf32 inputs, f32 accum.
__device__ __forceinline__ void mma_tf32(float c[4], const uint32_t a[4],
                                         const uint32_t b[2]) {
    asm volatile(
        "mma.sync.aligned.m16n8k8.row.col.f32.tf32.tf32.f32 "
        "{%0,%1,%2,%3}, {%4,%5,%6,%7}, {%8,%9}, {%0,%1,%2,%3};"
        : "+f"(c[0]), "+f"(c[1]), "+f"(c[2]), "+f"(c[3])
        : "r"(a[0]), "r"(a[1]), "r"(a[2]), "r"(a[3]), "r"(b[0]), "r"(b[1]));
}
__device__ __forceinline__ void cp_async16(uint32_t s, const void* g) {
    asm volatile("cp.async.ca.shared.global [%0], [%1], 16;"
                 :: "r"(s), "l"(g) : "memory");
}
__device__ __forceinline__ void cp_commit() {
    asm volatile("cp.async.commit_group;" ::: "memory");
}
template<int N> __device__ __forceinline__ void cp_wait() {
    asm volatile("cp.async.wait_group %0;" :: "n"(N) : "memory");
}

// ===========================================================================
// GEMM: C[M,512] = A[M,512] @ W[512,512]^T (+bias).  tf32 mma.sync.
// CTA 128x128, BK=32, cp.async double buffer, 8 warps (2m x 4n), warp 64x32.
// smem: fp32 tiles, pitch 36 floats (conflict-free fragment LDS).
// ===========================================================================
#define GBK    32
#define GPITCH 36
#define GA_BYTES (128 * GPITCH * 4)        // 18432
#define GSTAGE   (2 * GA_BYTES)            // A + W per stage = 36864
#define GEMM_SMEM (2 * GSTAGE)             // 73728

__global__ __launch_bounds__(256) void gemm_tc_kernel(
    const float* __restrict__ A, const float* __restrict__ W,
    const float* __restrict__ bias, float* __restrict__ C, int addBias)
{
    extern __shared__ char smc[];
    float* sf = (float*)smc;
    const uint32_t sb = smem_u32(smc);

    const int tid = threadIdx.x;
    const int w   = tid >> 5;
    const int lane = tid & 31;
    const int gid = lane >> 2;     // 0..7
    const int tig = lane & 3;      // 0..3
    const int wm  = (w >> 2) * 64; // warp m offset
    const int wn  = (w & 3) * 32;  // warp n offset
    const int m0  = blockIdx.y * 128;
    const int n0  = blockIdx.x * 128;

    // per-thread load coords: 128 rows x 8 float4 per tile
    const int lr = tid >> 1;            // row for iter base
    // each thread does 4 float4 per tile: idx = tid + 256*i
    float acc[4][4][4];
    #pragma unroll
    for (int mt = 0; mt < 4; mt++)
        #pragma unroll
        for (int nt = 0; nt < 4; nt++)
            #pragma unroll
            for (int q = 0; q < 4; q++) acc[mt][nt][q] = 0.f;
    (void)lr;

    auto stage_load = [&](int buf, int k0) {
        const uint32_t sA = sb + buf * GSTAGE;
        const uint32_t sW = sA + GA_BYTES;
        #pragma unroll
        for (int i = 0; i < 4; i++) {
            int idx = tid + 256 * i;
            int r  = idx >> 3;
            int c4 = (idx & 7) << 2;
            uint32_t off = (uint32_t)(r * GPITCH + c4) * 4u;
            cp_async16(sA + off, A + (size_t)(m0 + r) * DM + k0 + c4);
            cp_async16(sW + off, W + (size_t)(n0 + r) * DM + k0 + c4);
        }
        cp_commit();
    };

    const int NST = DM / GBK;   // 16
    stage_load(0, 0);
    stage_load(1, GBK);

    for (int ks = 0; ks < NST; ++ks) {
        const int buf = ks & 1;
        cp_wait<1>();
        __syncthreads();

        const float* As = sf + buf * (GSTAGE / 4);
        const float* Ws = As + (GA_BYTES / 4);

        #pragma unroll
        for (int kk = 0; kk < 4; kk++) {
            const int kb = kk * 8;
            uint32_t af[4][4];
            #pragma unroll
            for (int mt = 0; mt < 4; mt++) {
                int base = (wm + mt * 16 + gid) * GPITCH + kb + tig;
                af[mt][0] = f2tf32(As[base]);
                af[mt][1] = f2tf32(As[base + 8 * GPITCH]);
                af[mt][2] = f2tf32(As[base + 4]);
                af[mt][3] = f2tf32(As[base + 8 * GPITCH + 4]);
            }
            uint32_t bf[4][2];
            #pragma unroll
            for (int nt = 0; nt < 4; nt++) {
                int base = (wn + nt * 8 + gid) * GPITCH + kb + tig;
                bf[nt][0] = f2tf32(Ws[base]);
                bf[nt][1] = f2tf32(Ws[base + 4]);
            }
            #pragma unroll
            for (int mt = 0; mt < 4; mt++)
                #pragma unroll
                for (int nt = 0; nt < 4; nt++)
                    mma_tf32(acc[mt][nt], af[mt], bf[nt]);
        }
        __syncthreads();
        if (ks + 2 < NST) stage_load(buf, (ks + 2) * GBK);
    }

    // epilogue
    #pragma unroll
    for (int mt = 0; mt < 4; mt++) {
        const int r0 = m0 + wm + mt * 16 + gid;
        #pragma unroll
        for (int nt = 0; nt < 4; nt++) {
            const int col = n0 + wn + nt * 8 + 2 * tig;
            float b0 = 0.f, b1 = 0.f;
            if (addBias) { b0 = bias[col]; b1 = bias[col + 1]; }
            *(float2*)(C + (size_t)r0 * DM + col) =
                make_float2(acc[mt][nt][0] + b0, acc[mt][nt][1] + b1);
            *(float2*)(C + (size_t)(r0 + 8) * DM + col) =
                make_float2(acc[mt][nt][2] + b0, acc[mt][nt][3] + b1);
        }
    }
}

// ===========================================================================
// Flash attention, tf32 mma.sync for S = Q K^T and O += P V.
// CTA: 128 q rows x (b,h). 8 warps, warp w owns q rows [16w,16w+16).
// K/V tiles 64 wide. P staged through smem (warp-private rows).
// smem pitches: Q/K/P = 68 floats, V = 72 floats (conflict-free frag LDS).
// ===========================================================================
#define QS_OFF 0
#define KS_OFF (128 * 68)
#define VS_OFF (KS_OFF + 64 * 68)
#define PS_OFF (VS_OFF + 64 * 72)
#define ATTN_SMEM ((PS_OFF + 128 * 68) * 4)

__global__ __launch_bounds__(256) void attn_kernel(const float* __restrict__ bias)
{
    extern __shared__ float sm[];
    float* Qs = sm + QS_OFF;
    float* Ks = sm + KS_OFF;
    float* Vs = sm + VS_OFF;
    float* Ps = sm + PS_OFF;

    const int tid  = threadIdx.x;
    const int w    = tid >> 5;
    const int lane = tid & 31;
    const int gid  = lane >> 2;
    const int tig  = lane & 3;
    const int q0   = blockIdx.x * 128;
    const int h    = blockIdx.y;
    const int b    = blockIdx.z;

    // Load Q tile (128 x 64 fp32), row-major pitch 68
    {
        const float* Qg = g_Q + ((size_t)b * NQS + q0) * DM + h * DH;
        #pragma unroll
        for (int i = 0; i < 8; i++) {
            int idx = tid + 256 * i;        // 2048 float4
            int r  = idx >> 4;
            int c4 = (idx & 15) << 2;
            *(float4*)&Qs[r * 68 + c4] = *(const float4*)(Qg + (size_t)r * DM + c4);
        }
    }

    float o[8][4];
    #pragma unroll
    for (int nt = 0; nt < 8; nt++)
        #pragma unroll
        for (int q = 0; q < 4; q++) o[nt][q] = 0.f;
    float m_lo = -1e30f, m_hi = -1e30f, l_lo = 0.f, l_hi = 0.f;

    const float* biasLo = bias + ((size_t)b * NQS + q0 + 16 * w + gid) * NKS;
    const float* biasHi = biasLo + 8 * (size_t)NKS;

    for (int kb = 0; kb < NKS / 64; kb++) {
        const int k0 = kb * 64;
        __syncthreads();   // everyone done with previous K/V
        {
            const float* Kg = g_K + ((size_t)b * NKS + k0) * DM + h * DH;
            const float* Vg = g_V + ((size_t)b * NKS + k0) * DM + h * DH;
            #pragma unroll
            for (int i = 0; i < 4; i++) {
                int idx = tid + 256 * i;    // 1024 float4 per tile
                int r  = idx >> 4;
                int c4 = (idx & 15) << 2;
                *(float4*)&Ks[r * 68 + c4] = *(const float4*)(Kg + (size_t)r * DM + c4);
                *(float4*)&Vs[r * 72 + c4] = *(const float4*)(Vg + (size_t)r * DM + c4);
            }
        }
        __syncthreads();

        // ---- S = Q K^T : warp rows [16w,16w+16), cols 0..63 ----
        float s[8][4];
        #pragma unroll
        for (int nt = 0; nt < 8; nt++)
            #pragma unroll
            for (int q = 0; q < 4; q++) s[nt][q] = 0.f;

        #pragma unroll
        for (int kk = 0; kk < 8; kk++) {
            const int kbi = kk * 8;
            uint32_t af[4];
            {
                int base = (16 * w + gid) * 68 + kbi + tig;
                af[0] = f2tf32(Qs[base]);
                af[1] = f2tf32(Qs[base + 8 * 68]);
                af[2] = f2tf32(Qs[base + 4]);
                af[3] = f2tf32(Qs[base + 8 * 68 + 4]);
            }
            #pragma unroll
            for (int nt = 0; nt < 8; nt++) {
                uint32_t bf[2];
                int base = (nt * 8 + gid) * 68 + kbi + tig;
                bf[0] = f2tf32(Ks[base]);
                bf[1] = f2tf32(Ks[base + 4]);
                mma_tf32(s[nt], af, bf);
            }
        }

        // ---- scale + bias, online softmax (rows are quad-local) ----
        float rmLo = -1e30f, rmHi = -1e30f;
        #pragma unroll
        for (int nt = 0; nt < 8; nt++) {
            float2 bl = *(const float2*)(biasLo + k0 + nt * 8 + 2 * tig);
            float2 bh = *(const float2*)(biasHi + k0 + nt * 8 + 2 * tig);
            s[nt][0] = fmaf(s[nt][0], 0.125f, bl.x);
            s[nt][1] = fmaf(s[nt][1], 0.125f, bl.y);
            s[nt][2] = fmaf(s[nt][2], 0.125f, bh.x);
            s[nt][3] = fmaf(s[nt][3], 0.125f, bh.y);
            rmLo = fmaxf(rmLo, fmaxf(s[nt][0], s[nt][1]));
            rmHi = fmaxf(rmHi, fmaxf(s[nt][2], s[nt][3]));
        }
        rmLo = fmaxf(rmLo, __shfl_xor_sync(0xffffffffu, rmLo, 1));
        rmLo = fmaxf(rmLo, __shfl_xor_sync(0xffffffffu, rmLo, 2));
        rmHi = fmaxf(rmHi, __shfl_xor_sync(0xffffffffu, rmHi, 1));
        rmHi = fmaxf(rmHi, __shfl_xor_sync(0xffffffffu, rmHi, 2));

        const float mnLo = fmaxf(m_lo, rmLo);
        const float mnHi = fmaxf(m_hi, rmHi);
        const float corrLo = __expf(m_lo - mnLo);
        const float corrHi = __expf(m_hi - mnHi);
        m_lo = mnLo; m_hi = mnHi;

        float rsLo = 0.f, rsHi = 0.f;
        #pragma unroll
        for (int nt = 0; nt < 8; nt++) {
            float p0 = __expf(s[nt][0] - mnLo);
            float p1 = __expf(s[nt][1] - mnLo);
            float p2 = __expf(s[nt][2] - mnHi);
            float p3 = __expf(s[nt][3] - mnHi);
            rsLo += p0 + p1;
            rsHi += p2 + p3;
            // store P as tf32 bits (C-frag -> smem)
            int rl = (16 * w + gid) * 68 + nt * 8 + 2 * tig;
            int rh = rl + 8 * 68;
            *(float2*)&Ps[rl] = make_float2(__uint_as_float(f2tf32(p0)),
                                            __uint_as_float(f2tf32(p1)));
            *(float2*)&Ps[rh] = make_float2(__uint_as_float(f2tf32(p2)),
                                            __uint_as_float(f2tf32(p3)));
            #pragma unroll
            for (int q = 0; q < 2; q++) { o[nt][q] *= corrLo; o[nt][q + 2] *= corrHi; }
        }
        rsLo += __shfl_xor_sync(0xffffffffu, rsLo, 1);
        rsLo += __shfl_xor_sync(0xffffffffu, rsLo, 2);
        rsHi += __shfl_xor_sync(0xffffffffu, rsHi, 1);
        rsHi += __shfl_xor_sync(0xffffffffu, rsHi, 2);
        l_lo = l_lo * corrLo + rsLo;
        l_hi = l_hi * corrHi + rsHi;

        __syncwarp();   // P rows are warp-private: warp fence suffices

        // ---- O += P V ----
        #pragma unroll
        for (int kk = 0; kk < 8; kk++) {
            const int kbi = kk * 8;
            uint32_t af[4];
            {
                int base = (16 * w + gid) * 68 + kbi + tig;
                af[0] = __float_as_uint(Ps[base]);
                af[1] = __float_as_uint(Ps[base + 8 * 68]);
                af[2] = __float_as_uint(Ps[base + 4]);
                af[3] = __float_as_uint(Ps[base + 8 * 68 + 4]);
            }
            #pragma unroll
            for (int nt = 0; nt < 8; nt++) {
                uint32_t bf[2];
                int base = (kbi + tig) * 72 + nt * 8 + gid;
                bf[0] = f2tf32(Vs[base]);
                bf[1] = f2tf32(Vs[base + 4 * 72]);
                mma_tf32(o[nt], af, bf);
            }
        }
        __syncwarp();
    }

    // normalize + store
    const float invLo = 1.f / l_lo;
    const float invHi = 1.f / l_hi;
    const int rowLo = q0 + 16 * w + gid;
    float* OgLo = g_AO + ((size_t)b * NQS + rowLo) * DM + h * DH;
    float* OgHi = OgLo + 8 * (size_t)DM;
    #pragma unroll
    for (int nt = 0; nt < 8; nt++) {
        int col = nt * 8 + 2 * tig;
        *(float2*)(OgLo + col) = make_float2(o[nt][0] * invLo, o[nt][1] * invLo);
        *(float2*)(OgHi + col) = make_float2(o[nt][2] * invHi, o[nt][3] * invHi);
    }
}

// ---------------------------------------------------------------------------
// Launch
// ---------------------------------------------------------------------------
extern "C" void kernel_launch(void* const* d_in, const int* in_sizes, int n_in,
                              void* d_out, int out_size)
{
    const float* x    = (const float*)d_in[0];  // (4,1024,512)
    const float* ctx  = (const float*)d_in[1];  // (4,2048,512)
    const float* bias = (const float*)d_in[2];  // (4,1024,2048)
    const float* Wq   = (const float*)d_in[3];  // (512,512)
    const float* Wk   = (const float*)d_in[4];
    const float* Wv   = (const float*)d_in[5];
    const float* Wo   = (const float*)d_in[6];
    const float* bo   = (const float*)d_in[7];  // (512,)
    float* out = (float*)d_out;                 // (4,1024,512)

    cudaFuncSetAttribute(gemm_tc_kernel,
                         cudaFuncAttributeMaxDynamicSharedMemorySize, GEMM_SMEM);
    cudaFuncSetAttribute(attn_kernel,
                         cudaFuncAttributeMaxDynamicSharedMemorySize, ATTN_SMEM);

    float *gQ, *gK, *gV, *gAO;
    cudaGetSymbolAddress((void**)&gQ,  g_Q);
    cudaGetSymbolAddress((void**)&gK,  g_K);
    cudaGetSymbolAddress((void**)&gV,  g_V);
    cudaGetSymbolAddress((void**)&gAO, g_AO);

    dim3 blk(256);
    gemm_tc_kernel<<<dim3(4, (BATCH * NQS) / 128), blk, GEMM_SMEM>>>(x,   Wq, nullptr, gQ, 0);
    gemm_tc_kernel<<<dim3(4, (BATCH * NKS) / 128), blk, GEMM_SMEM>>>(ctx, Wk, nullptr, gK, 0);
    gemm_tc_kernel<<<dim3(4, (BATCH * NKS) / 128), blk, GEMM_SMEM>>>(ctx, Wv, nullptr, gV, 0);
    attn_kernel<<<dim3(NQS / 128, NHEADS, BATCH), blk, ATTN_SMEM>>>(bias);
    gemm_tc_kernel<<<dim3(4, (BATCH * NQS) / 128), blk, GEMM_SMEM>>>(gAO, Wo, bo, out, 1);
}

// round 4
// speedup vs baseline: 3.3244x; 1.1485x over previous
#include <cuda_runtime.h>
#include <cstdint>
#include <math.h>

#define NHEADS 8
#define DH     64
#define BATCH  4
#define NQS    1024
#define NKS    2048
#define DM     512

// Scratch in device globals. g_Q/g_K/g_V hold PACKED tf32 fragments (bit-cast
// floats) laid out in mma-fragment order; g_AO is row-major fp32.
__device__ float g_Q [(size_t)BATCH * NQS * DM];
__device__ float g_K [(size_t)BATCH * NKS * DM];
__device__ float g_V [(size_t)BATCH * NKS * DM];
__device__ float g_AO[(size_t)BATCH * NQS * DM];

// ===========================================================================
// Helpers
// ===========================================================================
__device__ __forceinline__ uint32_t smem_u32(const void* p) {
    uint32_t a;
    asm("{ .reg .u64 t; cvta.to.shared.u64 t, %1; cvt.u32.u64 %0, t; }"
        : "=r"(a) : "l"(p));
    return a;
}
__device__ __forceinline__ uint32_t f2tf32(float f) {
    uint32_t u;
    asm("cvt.rna.tf32.f32 %0, %1;" : "=r"(u) : "f"(f));
    return u;
}
__device__ __forceinline__ void mma_tf32(float c[4], const uint32_t a[4],
                                         uint32_t b0, uint32_t b1) {
    asm volatile(
        "mma.sync.aligned.m16n8k8.row.col.f32.tf32.tf32.f32 "
        "{%0,%1,%2,%3}, {%4,%5,%6,%7}, {%8,%9}, {%0,%1,%2,%3};"
        : "+f"(c[0]), "+f"(c[1]), "+f"(c[2]), "+f"(c[3])
        : "r"(a[0]), "r"(a[1]), "r"(a[2]), "r"(a[3]), "r"(b0), "r"(b1));
}
__device__ __forceinline__ void cp_async16(uint32_t s, const void* g) {
    asm volatile("cp.async.ca.shared.global [%0], [%1], 16;"
                 :: "r"(s), "l"(g) : "memory");
}
__device__ __forceinline__ void cp_commit() {
    asm volatile("cp.async.commit_group;" ::: "memory");
}
template<int N> __device__ __forceinline__ void cp_wait() {
    asm volatile("cp.async.wait_group %0;" :: "n"(N) : "memory");
}

// ===========================================================================
// GEMM: C[M,512] = A[M,512] @ W[512,512]^T.  tf32 mma.sync.
// CTA 128x128, BK=32, cp.async double buffer, 8 warps (2m x 4n), warp 64x32.
// MODE 0: plain fp32 store (+bias). MODE 1: Q-pack (x0.125, tf32, A-frag
// layout). MODE 2: K-pack (B-frag for S). MODE 3: V-pack (B-frag for PV).
// ===========================================================================
#define GBK    32
#define GPITCH 36
#define GA_BYTES (128 * GPITCH * 4)
#define GSTAGE   (2 * GA_BYTES)
#define GEMM_SMEM (2 * GSTAGE)

template<int MODE>
__global__ __launch_bounds__(256) void gemm_tc_kernel(
    const float* __restrict__ A, const float* __restrict__ W,
    const float* __restrict__ bias, float* __restrict__ C, int addBias)
{
    extern __shared__ char smc[];
    float* sf = (float*)smc;
    const uint32_t sb = smem_u32(smc);

    const int tid  = threadIdx.x;
    const int w    = tid >> 5;
    const int lane = tid & 31;
    const int gid  = lane >> 2;
    const int tig  = lane & 3;
    const int wm   = (w >> 2) * 64;
    const int wn   = (w & 3) * 32;
    const int m0   = blockIdx.y * 128;
    const int n0   = blockIdx.x * 128;

    float acc[4][4][4];
    #pragma unroll
    for (int mt = 0; mt < 4; mt++)
        #pragma unroll
        for (int nt = 0; nt < 4; nt++)
            #pragma unroll
            for (int q = 0; q < 4; q++) acc[mt][nt][q] = 0.f;

    auto stage_load = [&](int buf, int k0) {
        const uint32_t sA = sb + buf * GSTAGE;
        const uint32_t sW = sA + GA_BYTES;
        #pragma unroll
        for (int i = 0; i < 4; i++) {
            int idx = tid + 256 * i;
            int r  = idx >> 3;
            int c4 = (idx & 7) << 2;
            uint32_t off = (uint32_t)(r * GPITCH + c4) * 4u;
            cp_async16(sA + off, A + (size_t)(m0 + r) * DM + k0 + c4);
            cp_async16(sW + off, W + (size_t)(n0 + r) * DM + k0 + c4);
        }
        cp_commit();
    };

    const int NST = DM / GBK;
    stage_load(0, 0);
    stage_load(1, GBK);

    for (int ks = 0; ks < NST; ++ks) {
        const int buf = ks & 1;
        cp_wait<1>();
        __syncthreads();

        const float* As = sf + buf * (GSTAGE / 4);
        const float* Ws = As + (GA_BYTES / 4);

        #pragma unroll
        for (int kk = 0; kk < 4; kk++) {
            const int kb = kk * 8;
            uint32_t af[4][4];
            #pragma unroll
            for (int mt = 0; mt < 4; mt++) {
                int base = (wm + mt * 16 + gid) * GPITCH + kb + tig;
                af[mt][0] = f2tf32(As[base]);
                af[mt][1] = f2tf32(As[base + 8 * GPITCH]);
                af[mt][2] = f2tf32(As[base + 4]);
                af[mt][3] = f2tf32(As[base + 8 * GPITCH + 4]);
            }
            uint32_t bf[4][2];
            #pragma unroll
            for (int nt = 0; nt < 4; nt++) {
                int base = (wn + nt * 8 + gid) * GPITCH + kb + tig;
                bf[nt][0] = f2tf32(Ws[base]);
                bf[nt][1] = f2tf32(Ws[base + 4]);
            }
            #pragma unroll
            for (int mt = 0; mt < 4; mt++)
                #pragma unroll
                for (int nt = 0; nt < 4; nt++)
                    mma_tf32(acc[mt][nt], af[mt], bf[nt][0], bf[nt][1]);
        }
        __syncthreads();
        if (ks + 2 < NST) stage_load(buf, (ks + 2) * GBK);
    }

    // ---------------- epilogue ----------------
    if (MODE == 0) {
        #pragma unroll
        for (int mt = 0; mt < 4; mt++) {
            const int r0 = m0 + wm + mt * 16 + gid;
            #pragma unroll
            for (int nt = 0; nt < 4; nt++) {
                const int col = n0 + wn + nt * 8 + 2 * tig;
                float b0 = 0.f, b1 = 0.f;
                if (addBias) { b0 = bias[col]; b1 = bias[col + 1]; }
                *(float2*)(C + (size_t)r0 * DM + col) =
                    make_float2(acc[mt][nt][0] + b0, acc[mt][nt][1] + b1);
                *(float2*)(C + (size_t)(r0 + 8) * DM + col) =
                    make_float2(acc[mt][nt][2] + b0, acc[mt][nt][3] + b1);
            }
        }
    } else {
        #pragma unroll
        for (int mt = 0; mt < 4; mt++) {
            #pragma unroll
            for (int nt = 0; nt < 4; nt++) {
                #pragma unroll
                for (int q = 0; q < 4; q++) {
                    const int m   = m0 + wm + mt * 16 + gid + 8 * (q >> 1);
                    const int col = n0 + wn + nt * 8 + 2 * tig + (q & 1);
                    const int h = col >> 6, d = col & 63;
                    float val = acc[mt][nt][q];
                    size_t idx;
                    if (MODE == 1) {
                        // Q: A-frag pack, pre-scaled
                        int b  = m >> 10, qq = m & 1023;
                        int lane_t = (qq & 7) * 4 + (d & 3);
                        idx = ((((size_t)((b * 8 + h) * 64 + (qq >> 4)) * 8
                                 + (d >> 3)) * 32 + lane_t) * 4)
                              + ((qq >> 3) & 1) + 2 * ((d >> 2) & 1);
                        val *= 0.125f;
                    } else if (MODE == 2) {
                        // K: B-frag pack for S = Q K^T
                        int b = m >> 11, n = m & 2047;
                        int lane_t = (n & 7) * 4 + (d & 3);
                        idx = ((size_t)((b * 32 + (n >> 6)) * 8 + h) * 4096)
                              + (((d >> 3) * 8 + ((n & 63) >> 3)) * 32 + lane_t) * 2
                              + ((d >> 2) & 1);
                    } else {
                        // V: B-frag pack for O = P V
                        int b = m >> 11, n = m & 2047;
                        int kr = n & 63;
                        int lane_t = (d & 7) * 4 + (kr & 3);
                        idx = ((size_t)((b * 32 + (n >> 6)) * 8 + h) * 4096)
                              + (((kr >> 3) * 8 + (d >> 3)) * 32 + lane_t) * 2
                              + ((kr >> 2) & 1);
                    }
                    C[idx] = __uint_as_float(f2tf32(val));
                }
            }
        }
    }
}

// ===========================================================================
// Flash attention on packed tf32 fragments.
// CTA: 128 q rows x (b,h); 8 warps, warp w owns rows [16w,16w+16).
// smem (floats): Kp[4096] | Vp[4096] | Pp[8*1024] | Qp[8*1024]  = 96KB.
// All fragment loads are LDS.128 / LDS.64, conflict-free.
// ===========================================================================
#define KP 0
#define VP 4096
#define PP 8192
#define QP 16384
#define ATTN_SMEM (24576 * 4)

__global__ __launch_bounds__(256, 2) void attn_kernel(const float* __restrict__ bias)
{
    extern __shared__ float sm[];
    const uint32_t sb = smem_u32(sm);

    const int tid  = threadIdx.x;
    const int w    = tid >> 5;
    const int lane = tid & 31;
    const int gid  = lane >> 2;
    const int tig  = lane & 3;
    const int q0   = blockIdx.x * 128;
    const int h    = blockIdx.y;
    const int b    = blockIdx.z;

    // Q fragments for this warp's 16 rows: contiguous 4KB
    {
        const float* gq = g_Q + ((size_t)((b * 8 + h) * 64 + blockIdx.x * 8 + w)) * 1024;
        #pragma unroll
        for (int i = 0; i < 8; i++)
            cp_async16(sb + (QP + w * 1024 + i * 128 + lane * 4) * 4,
                       gq + i * 128 + lane * 4);
    }
    // K/V tile 0
    {
        const float* gk = g_K + ((size_t)(b * 32 + 0) * 8 + h) * 4096;
        const float* gv = g_V + ((size_t)(b * 32 + 0) * 8 + h) * 4096;
        #pragma unroll
        for (int i = 0; i < 4; i++) {
            int off = i * 1024 + tid * 4;
            cp_async16(sb + (KP + off) * 4, gk + off);
            cp_async16(sb + (VP + off) * 4, gv + off);
        }
    }
    cp_commit();

    float o[8][4];
    #pragma unroll
    for (int nt = 0; nt < 8; nt++)
        #pragma unroll
        for (int q = 0; q < 4; q++) o[nt][q] = 0.f;
    float m_lo = -1e30f, m_hi = -1e30f, l_lo = 0.f, l_hi = 0.f;

    const float* biasLo = bias + ((size_t)b * NQS + q0 + 16 * w + gid) * NKS;
    const float* biasHi = biasLo + 8 * (size_t)NKS;

    const int pbase = PP + w * 1024;
    const int qbase = QP + w * 1024;

    for (int kb = 0; kb < NKS / 64; kb++) {
        const int k0 = kb * 64;
        cp_wait<0>();
        __syncthreads();

        // ---- S = Q K^T ----
        float s[8][4];
        #pragma unroll
        for (int nt = 0; nt < 8; nt++)
            #pragma unroll
            for (int q = 0; q < 4; q++) s[nt][q] = 0.f;

        #pragma unroll
        for (int kk = 0; kk < 8; kk++) {
            float4 a4 = *(const float4*)&sm[qbase + kk * 128 + lane * 4];
            uint32_t af[4] = {__float_as_uint(a4.x), __float_as_uint(a4.y),
                              __float_as_uint(a4.z), __float_as_uint(a4.w)};
            #pragma unroll
            for (int nt = 0; nt < 8; nt++) {
                float2 k2 = *(const float2*)&sm[KP + (kk * 8 + nt) * 64 + lane * 2];
                mma_tf32(s[nt], af, __float_as_uint(k2.x), __float_as_uint(k2.y));
            }
        }

        // ---- + bias, online softmax (Q pre-scaled) ----
        float rmLo = -1e30f, rmHi = -1e30f;
        #pragma unroll
        for (int nt = 0; nt < 8; nt++) {
            float2 bl = *(const float2*)(biasLo + k0 + nt * 8 + 2 * tig);
            float2 bh = *(const float2*)(biasHi + k0 + nt * 8 + 2 * tig);
            s[nt][0] += bl.x;  s[nt][1] += bl.y;
            s[nt][2] += bh.x;  s[nt][3] += bh.y;
            rmLo = fmaxf(rmLo, fmaxf(s[nt][0], s[nt][1]));
            rmHi = fmaxf(rmHi, fmaxf(s[nt][2], s[nt][3]));
        }
        rmLo = fmaxf(rmLo, __shfl_xor_sync(0xffffffffu, rmLo, 1));
        rmLo = fmaxf(rmLo, __shfl_xor_sync(0xffffffffu, rmLo, 2));
        rmHi = fmaxf(rmHi, __shfl_xor_sync(0xffffffffu, rmHi, 1));
        rmHi = fmaxf(rmHi, __shfl_xor_sync(0xffffffffu, rmHi, 2));

        const float mnLo = fmaxf(m_lo, rmLo);
        const float mnHi = fmaxf(m_hi, rmHi);
        const float corrLo = __expf(m_lo - mnLo);
        const float corrHi = __expf(m_hi - mnHi);
        m_lo = mnLo; m_hi = mnHi;

        const int c0 = 2 * tig, c1 = 2 * tig + 1;
        const int a0 = pbase + (gid * 4 + (c0 & 3)) * 4 + 2 * (c0 >> 2);
        const int a1 = pbase + (gid * 4 + (c1 & 3)) * 4 + 2 * (c1 >> 2);

        float rsLo = 0.f, rsHi = 0.f;
        #pragma unroll
        for (int nt = 0; nt < 8; nt++) {
            float p0 = __expf(s[nt][0] - mnLo);
            float p1 = __expf(s[nt][1] - mnLo);
            float p2 = __expf(s[nt][2] - mnHi);
            float p3 = __expf(s[nt][3] - mnHi);
            rsLo += p0 + p1;
            rsHi += p2 + p3;
            *(float2*)&sm[a0 + nt * 128] =
                make_float2(__uint_as_float(f2tf32(p0)), __uint_as_float(f2tf32(p2)));
            *(float2*)&sm[a1 + nt * 128] =
                make_float2(__uint_as_float(f2tf32(p1)), __uint_as_float(f2tf32(p3)));
            o[nt][0] *= corrLo; o[nt][1] *= corrLo;
            o[nt][2] *= corrHi; o[nt][3] *= corrHi;
        }
        rsLo += __shfl_xor_sync(0xffffffffu, rsLo, 1);
        rsLo += __shfl_xor_sync(0xffffffffu, rsLo, 2);
        rsHi += __shfl_xor_sync(0xffffffffu, rsHi, 1);
        rsHi += __shfl_xor_sync(0xffffffffu, rsHi, 2);
        l_lo = l_lo * corrLo + rsLo;
        l_hi = l_hi * corrHi + rsHi;

        __syncwarp();   // P region is warp-private

        // ---- O += P V ----
        #pragma unroll
        for (int kk = 0; kk < 8; kk++) {
            float4 a4 = *(const float4*)&sm[pbase + kk * 128 + lane * 4];
            uint32_t af[4] = {__float_as_uint(a4.x), __float_as_uint(a4.y),
                              __float_as_uint(a4.z), __float_as_uint(a4.w)};
            #pragma unroll
            for (int nt = 0; nt < 8; nt++) {
                float2 v2 = *(const float2*)&sm[VP + (kk * 8 + nt) * 64 + lane * 2];
                mma_tf32(o[nt], af, __float_as_uint(v2.x), __float_as_uint(v2.y));
            }
        }

        __syncthreads();   // done reading K/V before overwrite
        if (kb + 1 < NKS / 64) {
            const float* gk = g_K + ((size_t)(b * 32 + kb + 1) * 8 + h) * 4096;
            const float* gv = g_V + ((size_t)(b * 32 + kb + 1) * 8 + h) * 4096;
            #pragma unroll
            for (int i = 0; i < 4; i++) {
                int off = i * 1024 + tid * 4;
                cp_async16(sb + (KP + off) * 4, gk + off);
                cp_async16(sb + (VP + off) * 4, gv + off);
            }
            cp_commit();
        }
    }

    // normalize + store (row-major g_AO for the output GEMM)
    const float invLo = 1.f / l_lo;
    const float invHi = 1.f / l_hi;
    const int rowLo = q0 + 16 * w + gid;
    float* OgLo = g_AO + ((size_t)b * NQS + rowLo) * DM + h * DH;
    float* OgHi = OgLo + 8 * (size_t)DM;
    #pragma unroll
    for (int nt = 0; nt < 8; nt++) {
        int col = nt * 8 + 2 * tig;
        *(float2*)(OgLo + col) = make_float2(o[nt][0] * invLo, o[nt][1] * invLo);
        *(float2*)(OgHi + col) = make_float2(o[nt][2] * invHi, o[nt][3] * invHi);
    }
}

// ---------------------------------------------------------------------------
// Launch
// ---------------------------------------------------------------------------
extern "C" void kernel_launch(void* const* d_in, const int* in_sizes, int n_in,
                              void* d_out, int out_size)
{
    const float* x    = (const float*)d_in[0];
    const float* ctx  = (const float*)d_in[1];
    const float* bias = (const float*)d_in[2];
    const float* Wq   = (const float*)d_in[3];
    const float* Wk   = (const float*)d_in[4];
    const float* Wv   = (const float*)d_in[5];
    const float* Wo   = (const float*)d_in[6];
    const float* bo   = (const float*)d_in[7];
    float* out = (float*)d_out;

    cudaFuncSetAttribute(gemm_tc_kernel<0>,
                         cudaFuncAttributeMaxDynamicSharedMemorySize, GEMM_SMEM);
    cudaFuncSetAttribute(gemm_tc_kernel<1>,
                         cudaFuncAttributeMaxDynamicSharedMemorySize, GEMM_SMEM);
    cudaFuncSetAttribute(gemm_tc_kernel<2>,
                         cudaFuncAttributeMaxDynamicSharedMemorySize, GEMM_SMEM);
    cudaFuncSetAttribute(gemm_tc_kernel<3>,
                         cudaFuncAttributeMaxDynamicSharedMemorySize, GEMM_SMEM);
    cudaFuncSetAttribute(attn_kernel,
                         cudaFuncAttributeMaxDynamicSharedMemorySize, ATTN_SMEM);

    float *gQ, *gK, *gV, *gAO;
    cudaGetSymbolAddress((void**)&gQ,  g_Q);
    cudaGetSymbolAddress((void**)&gK,  g_K);
    cudaGetSymbolAddress((void**)&gV,  g_V);
    cudaGetSymbolAddress((void**)&gAO, g_AO);

    dim3 blk(256);
    gemm_tc_kernel<1><<<dim3(4, (BATCH * NQS) / 128), blk, GEMM_SMEM>>>(x,   Wq, nullptr, gQ, 0);
    gemm_tc_kernel<2><<<dim3(4, (BATCH * NKS) / 128), blk, GEMM_SMEM>>>(ctx, Wk, nullptr, gK, 0);
    gemm_tc_kernel<3><<<dim3(4, (BATCH * NKS) / 128), blk, GEMM_SMEM>>>(ctx, Wv, nullptr, gV, 0);
    attn_kernel<<<dim3(NQS / 128, NHEADS, BATCH), blk, ATTN_SMEM>>>(bias);
    gemm_tc_kernel<0><<<dim3(4, (BATCH * NQS) / 128), blk, GEMM_SMEM>>>(gAO, Wo, bo, out, 1);
}

// round 5
// speedup vs baseline: 3.6879x; 1.1093x over previous
#include <cuda_runtime.h>
#include <cstdint>
#include <math.h>

#define NHEADS 8
#define DH     64
#define BATCH  4
#define NQS    1024
#define NKS    2048
#define DM     512

// Scratch in device globals. g_Q/g_K/g_V hold PACKED tf32 fragments (bit-cast
// floats) laid out in mma-fragment order; g_AO is row-major fp32.
__device__ float g_Q [(size_t)BATCH * NQS * DM];
__device__ float g_K [(size_t)BATCH * NKS * DM];
__device__ float g_V [(size_t)BATCH * NKS * DM];
__device__ float g_AO[(size_t)BATCH * NQS * DM];

// ===========================================================================
// Helpers
// ===========================================================================
__device__ __forceinline__ uint32_t smem_u32(const void* p) {
    uint32_t a;
    asm("{ .reg .u64 t; cvta.to.shared.u64 t, %1; cvt.u32.u64 %0, t; }"
        : "=r"(a) : "l"(p));
    return a;
}
__device__ __forceinline__ uint32_t f2tf32(float f) {
    uint32_t u;
    asm("cvt.rna.tf32.f32 %0, %1;" : "=r"(u) : "f"(f));
    return u;
}
__device__ __forceinline__ void mma_tf32(float c[4], const uint32_t a[4],
                                         uint32_t b0, uint32_t b1) {
    asm volatile(
        "mma.sync.aligned.m16n8k8.row.col.f32.tf32.tf32.f32 "
        "{%0,%1,%2,%3}, {%4,%5,%6,%7}, {%8,%9}, {%0,%1,%2,%3};"
        : "+f"(c[0]), "+f"(c[1]), "+f"(c[2]), "+f"(c[3])
        : "r"(a[0]), "r"(a[1]), "r"(a[2]), "r"(a[3]), "r"(b0), "r"(b1));
}
__device__ __forceinline__ void cp_async16(uint32_t s, const void* g) {
    asm volatile("cp.async.ca.shared.global [%0], [%1], 16;"
                 :: "r"(s), "l"(g) : "memory");
}
__device__ __forceinline__ void cp_commit() {
    asm volatile("cp.async.commit_group;" ::: "memory");
}
template<int N> __device__ __forceinline__ void cp_wait() {
    asm volatile("cp.async.wait_group %0;" :: "n"(N) : "memory");
}

// ===========================================================================
// GEMM: C[M,512] = A[M,512] @ W[512,512]^T.  tf32 mma.sync.
// CTA 128x128, BK=32, cp.async double buffer, 8 warps (2m x 4n), warp 64x32.
// MODE 0: plain fp32 store (+bias). MODE 1: Q-pack (x0.125, tf32, A-frag
// layout). MODE 2: K-pack (B-frag for S). MODE 3: V-pack (B-frag for PV).
// ===========================================================================
#define GBK    32
#define GPITCH 36
#define GA_BYTES (128 * GPITCH * 4)
#define GSTAGE   (2 * GA_BYTES)
#define GEMM_SMEM (2 * GSTAGE)

template<int MODE>
__global__ __launch_bounds__(256) void gemm_tc_kernel(
    const float* __restrict__ A, const float* __restrict__ W,
    const float* __restrict__ bias, float* __restrict__ C, int addBias)
{
    extern __shared__ char smc[];
    float* sf = (float*)smc;
    const uint32_t sb = smem_u32(smc);

    const int tid  = threadIdx.x;
    const int w    = tid >> 5;
    const int lane = tid & 31;
    const int gid  = lane >> 2;
    const int tig  = lane & 3;
    const int wm   = (w >> 2) * 64;
    const int wn   = (w & 3) * 32;
    const int m0   = blockIdx.y * 128;
    const int n0   = blockIdx.x * 128;

    float acc[4][4][4];
    #pragma unroll
    for (int mt = 0; mt < 4; mt++)
        #pragma unroll
        for (int nt = 0; nt < 4; nt++)
            #pragma unroll
            for (int q = 0; q < 4; q++) acc[mt][nt][q] = 0.f;

    auto stage_load = [&](int buf, int k0) {
        const uint32_t sA = sb + buf * GSTAGE;
        const uint32_t sW = sA + GA_BYTES;
        #pragma unroll
        for (int i = 0; i < 4; i++) {
            int idx = tid + 256 * i;
            int r  = idx >> 3;
            int c4 = (idx & 7) << 2;
            uint32_t off = (uint32_t)(r * GPITCH + c4) * 4u;
            cp_async16(sA + off, A + (size_t)(m0 + r) * DM + k0 + c4);
            cp_async16(sW + off, W + (size_t)(n0 + r) * DM + k0 + c4);
        }
        cp_commit();
    };

    const int NST = DM / GBK;
    stage_load(0, 0);
    stage_load(1, GBK);

    for (int ks = 0; ks < NST; ++ks) {
        const int buf = ks & 1;
        cp_wait<1>();
        __syncthreads();

        const float* As = sf + buf * (GSTAGE / 4);
        const float* Ws = As + (GA_BYTES / 4);

        #pragma unroll
        for (int kk = 0; kk < 4; kk++) {
            const int kb = kk * 8;
            uint32_t af[4][4];
            #pragma unroll
            for (int mt = 0; mt < 4; mt++) {
                int base = (wm + mt * 16 + gid) * GPITCH + kb + tig;
                af[mt][0] = f2tf32(As[base]);
                af[mt][1] = f2tf32(As[base + 8 * GPITCH]);
                af[mt][2] = f2tf32(As[base + 4]);
                af[mt][3] = f2tf32(As[base + 8 * GPITCH + 4]);
            }
            uint32_t bf[4][2];
            #pragma unroll
            for (int nt = 0; nt < 4; nt++) {
                int base = (wn + nt * 8 + gid) * GPITCH + kb + tig;
                bf[nt][0] = f2tf32(Ws[base]);
                bf[nt][1] = f2tf32(Ws[base + 4]);
            }
            #pragma unroll
            for (int mt = 0; mt < 4; mt++)
                #pragma unroll
                for (int nt = 0; nt < 4; nt++)
                    mma_tf32(acc[mt][nt], af[mt], bf[nt][0], bf[nt][1]);
        }
        __syncthreads();
        if (ks + 2 < NST) stage_load(buf, (ks + 2) * GBK);
    }

    // ---------------- epilogue ----------------
    if (MODE == 0) {
        #pragma unroll
        for (int mt = 0; mt < 4; mt++) {
            const int r0 = m0 + wm + mt * 16 + gid;
            #pragma unroll
            for (int nt = 0; nt < 4; nt++) {
                const int col = n0 + wn + nt * 8 + 2 * tig;
                float b0 = 0.f, b1 = 0.f;
                if (addBias) { b0 = bias[col]; b1 = bias[col + 1]; }
                *(float2*)(C + (size_t)r0 * DM + col) =
                    make_float2(acc[mt][nt][0] + b0, acc[mt][nt][1] + b1);
                *(float2*)(C + (size_t)(r0 + 8) * DM + col) =
                    make_float2(acc[mt][nt][2] + b0, acc[mt][nt][3] + b1);
            }
        }
    } else {
        #pragma unroll
        for (int mt = 0; mt < 4; mt++) {
            #pragma unroll
            for (int nt = 0; nt < 4; nt++) {
                #pragma unroll
                for (int q = 0; q < 4; q++) {
                    const int m   = m0 + wm + mt * 16 + gid + 8 * (q >> 1);
                    const int col = n0 + wn + nt * 8 + 2 * tig + (q & 1);
                    const int h = col >> 6, d = col & 63;
                    float val = acc[mt][nt][q];
                    size_t idx;
                    if (MODE == 1) {
                        // Q: A-frag pack, pre-scaled
                        int b  = m >> 10, qq = m & 1023;
                        int lane_t = (qq & 7) * 4 + (d & 3);
                        idx = ((((size_t)((b * 8 + h) * 64 + (qq >> 4)) * 8
                                 + (d >> 3)) * 32 + lane_t) * 4)
                              + ((qq >> 3) & 1) + 2 * ((d >> 2) & 1);
                        val *= 0.125f;
                    } else if (MODE == 2) {
                        // K: B-frag pack for S = Q K^T
                        int b = m >> 11, n = m & 2047;
                        int lane_t = (n & 7) * 4 + (d & 3);
                        idx = ((size_t)((b * 32 + (n >> 6)) * 8 + h) * 4096)
                              + (((d >> 3) * 8 + ((n & 63) >> 3)) * 32 + lane_t) * 2
                              + ((d >> 2) & 1);
                    } else {
                        // V: B-frag pack for O = P V
                        int b = m >> 11, n = m & 2047;
                        int kr = n & 63;
                        int lane_t = (d & 7) * 4 + (kr & 3);
                        idx = ((size_t)((b * 32 + (n >> 6)) * 8 + h) * 4096)
                              + (((kr >> 3) * 8 + (d >> 3)) * 32 + lane_t) * 2
                              + ((kr >> 2) & 1);
                    }
                    C[idx] = __uint_as_float(f2tf32(val));
                }
            }
        }
    }
}

// ===========================================================================
// Flash attention on packed tf32 fragments.
// CTA: 128 q rows x (b,h); 4 warps x 32 rows each (two 16-row m-tiles), so
// every K/V B-fragment load feeds TWO mmas (halves the dominant smem traffic).
// smem (floats): Kp[4096] | Vp[4096] | Pp[4*2048] | Qp[4*2048] = 96KB.
// ===========================================================================
#define KP 0
#define VP 4096
#define PP 8192
#define QP 16384
#define ATTN_SMEM (24576 * 4)

__global__ __launch_bounds__(128, 2) void attn_kernel(const float* __restrict__ bias)
{
    extern __shared__ float sm[];
    const uint32_t sb = smem_u32(sm);

    const int tid  = threadIdx.x;
    const int w    = tid >> 5;      // 0..3
    const int lane = tid & 31;
    const int gid  = lane >> 2;
    const int tig  = lane & 3;
    const int q0   = blockIdx.x * 128;
    const int h    = blockIdx.y;
    const int b    = blockIdx.z;

    // Q fragments: warp w owns 16-row blocks (2w, 2w+1) -> 8KB contiguous
    {
        const float* gq = g_Q
            + ((size_t)((b * 8 + h) * 64 + blockIdx.x * 8 + 2 * w)) * 1024;
        #pragma unroll
        for (int i = 0; i < 16; i++)
            cp_async16(sb + (QP + w * 2048 + i * 128 + lane * 4) * 4,
                       gq + i * 128 + lane * 4);
    }
    // K/V tile 0 (16KB each, 128 threads)
    {
        const float* gk = g_K + ((size_t)(b * 32 + 0) * 8 + h) * 4096;
        const float* gv = g_V + ((size_t)(b * 32 + 0) * 8 + h) * 4096;
        #pragma unroll
        for (int i = 0; i < 8; i++) {
            int off = i * 512 + tid * 4;
            cp_async16(sb + (KP + off) * 4, gk + off);
            cp_async16(sb + (VP + off) * 4, gv + off);
        }
    }
    cp_commit();

    float o[2][8][4];
    #pragma unroll
    for (int mt = 0; mt < 2; mt++)
        #pragma unroll
        for (int nt = 0; nt < 8; nt++)
            #pragma unroll
            for (int q = 0; q < 4; q++) o[mt][nt][q] = 0.f;
    float mx[2][2] = {{-1e30f, -1e30f}, {-1e30f, -1e30f}};
    float ls[2][2] = {{0.f, 0.f}, {0.f, 0.f}};

    const int pbase = PP + w * 2048;
    const int qbase = QP + w * 2048;
    // P store addresses (A-frag layout), per column parity
    const int c0 = 2 * tig, c1 = 2 * tig + 1;
    const int pa0 = pbase + (gid * 4 + (c0 & 3)) * 4 + 2 * (c0 >> 2);
    const int pa1 = pbase + (gid * 4 + (c1 & 3)) * 4 + 2 * (c1 >> 2);

    for (int kb = 0; kb < NKS / 64; kb++) {
        const int k0 = kb * 64;
        cp_wait<0>();
        __syncthreads();

        // ---- S = Q K^T : 32 rows x 64 cols per warp ----
        float s[2][8][4];
        #pragma unroll
        for (int mt = 0; mt < 2; mt++)
            #pragma unroll
            for (int nt = 0; nt < 8; nt++)
                #pragma unroll
                for (int q = 0; q < 4; q++) s[mt][nt][q] = 0.f;

        #pragma unroll
        for (int kk = 0; kk < 8; kk++) {
            uint32_t af[2][4];
            #pragma unroll
            for (int mt = 0; mt < 2; mt++) {
                float4 a4 = *(const float4*)&sm[qbase + mt * 1024 + kk * 128 + lane * 4];
                af[mt][0] = __float_as_uint(a4.x); af[mt][1] = __float_as_uint(a4.y);
                af[mt][2] = __float_as_uint(a4.z); af[mt][3] = __float_as_uint(a4.w);
            }
            #pragma unroll
            for (int nt = 0; nt < 8; nt++) {
                float2 k2 = *(const float2*)&sm[KP + (kk * 8 + nt) * 64 + lane * 2];
                uint32_t b0 = __float_as_uint(k2.x), b1 = __float_as_uint(k2.y);
                mma_tf32(s[0][nt], af[0], b0, b1);
                mma_tf32(s[1][nt], af[1], b0, b1);
            }
        }

        // ---- + bias, online softmax, P store (per m-tile) ----
        #pragma unroll
        for (int mt = 0; mt < 2; mt++) {
            const float* bLo = bias
                + ((size_t)b * NQS + q0 + 32 * w + 16 * mt + gid) * NKS + k0;
            const float* bHi = bLo + 8 * (size_t)NKS;

            float rmLo = -1e30f, rmHi = -1e30f;
            #pragma unroll
            for (int nt = 0; nt < 8; nt++) {
                float2 bl = *(const float2*)(bLo + nt * 8 + 2 * tig);
                float2 bh = *(const float2*)(bHi + nt * 8 + 2 * tig);
                s[mt][nt][0] += bl.x;  s[mt][nt][1] += bl.y;
                s[mt][nt][2] += bh.x;  s[mt][nt][3] += bh.y;
                rmLo = fmaxf(rmLo, fmaxf(s[mt][nt][0], s[mt][nt][1]));
                rmHi = fmaxf(rmHi, fmaxf(s[mt][nt][2], s[mt][nt][3]));
            }
            rmLo = fmaxf(rmLo, __shfl_xor_sync(0xffffffffu, rmLo, 1));
            rmLo = fmaxf(rmLo, __shfl_xor_sync(0xffffffffu, rmLo, 2));
            rmHi = fmaxf(rmHi, __shfl_xor_sync(0xffffffffu, rmHi, 1));
            rmHi = fmaxf(rmHi, __shfl_xor_sync(0xffffffffu, rmHi, 2));

            const float mnLo = fmaxf(mx[mt][0], rmLo);
            const float mnHi = fmaxf(mx[mt][1], rmHi);
            const float corrLo = __expf(mx[mt][0] - mnLo);
            const float corrHi = __expf(mx[mt][1] - mnHi);
            mx[mt][0] = mnLo; mx[mt][1] = mnHi;

            float rsLo = 0.f, rsHi = 0.f;
            #pragma unroll
            for (int nt = 0; nt < 8; nt++) {
                float p0 = __expf(s[mt][nt][0] - mnLo);
                float p1 = __expf(s[mt][nt][1] - mnLo);
                float p2 = __expf(s[mt][nt][2] - mnHi);
                float p3 = __expf(s[mt][nt][3] - mnHi);
                rsLo += p0 + p1;
                rsHi += p2 + p3;
                *(float2*)&sm[pa0 + mt * 1024 + nt * 128] =
                    make_float2(__uint_as_float(f2tf32(p0)),
                                __uint_as_float(f2tf32(p2)));
                *(float2*)&sm[pa1 + mt * 1024 + nt * 128] =
                    make_float2(__uint_as_float(f2tf32(p1)),
                                __uint_as_float(f2tf32(p3)));
                o[mt][nt][0] *= corrLo; o[mt][nt][1] *= corrLo;
                o[mt][nt][2] *= corrHi; o[mt][nt][3] *= corrHi;
            }
            rsLo += __shfl_xor_sync(0xffffffffu, rsLo, 1);
            rsLo += __shfl_xor_sync(0xffffffffu, rsLo, 2);
            rsHi += __shfl_xor_sync(0xffffffffu, rsHi, 1);
            rsHi += __shfl_xor_sync(0xffffffffu, rsHi, 2);
            ls[mt][0] = ls[mt][0] * corrLo + rsLo;
            ls[mt][1] = ls[mt][1] * corrHi + rsHi;
        }

        __syncwarp();   // P region is warp-private

        // ---- O += P V ----
        #pragma unroll
        for (int kk = 0; kk < 8; kk++) {
            uint32_t af[2][4];
            #pragma unroll
            for (int mt = 0; mt < 2; mt++) {
                float4 a4 = *(const float4*)&sm[pbase + mt * 1024 + kk * 128 + lane * 4];
                af[mt][0] = __float_as_uint(a4.x); af[mt][1] = __float_as_uint(a4.y);
                af[mt][2] = __float_as_uint(a4.z); af[mt][3] = __float_as_uint(a4.w);
            }
            #pragma unroll
            for (int nt = 0; nt < 8; nt++) {
                float2 v2 = *(const float2*)&sm[VP + (kk * 8 + nt) * 64 + lane * 2];
                uint32_t b0 = __float_as_uint(v2.x), b1 = __float_as_uint(v2.y);
                mma_tf32(o[0][nt], af[0], b0, b1);
                mma_tf32(o[1][nt], af[1], b0, b1);
            }
        }

        __syncthreads();   // done reading K/V before overwrite
        if (kb + 1 < NKS / 64) {
            const float* gk = g_K + ((size_t)(b * 32 + kb + 1) * 8 + h) * 4096;
            const float* gv = g_V + ((size_t)(b * 32 + kb + 1) * 8 + h) * 4096;
            #pragma unroll
            for (int i = 0; i < 8; i++) {
                int off = i * 512 + tid * 4;
                cp_async16(sb + (KP + off) * 4, gk + off);
                cp_async16(sb + (VP + off) * 4, gv + off);
            }
            cp_commit();
        }
    }

    // normalize + store (row-major g_AO for the output GEMM)
    #pragma unroll
    for (int mt = 0; mt < 2; mt++) {
        const float invLo = 1.f / ls[mt][0];
        const float invHi = 1.f / ls[mt][1];
        const int rowLo = q0 + 32 * w + 16 * mt + gid;
        float* OgLo = g_AO + ((size_t)b * NQS + rowLo) * DM + h * DH;
        float* OgHi = OgLo + 8 * (size_t)DM;
        #pragma unroll
        for (int nt = 0; nt < 8; nt++) {
            int col = nt * 8 + 2 * tig;
            *(float2*)(OgLo + col) =
                make_float2(o[mt][nt][0] * invLo, o[mt][nt][1] * invLo);
            *(float2*)(OgHi + col) =
                make_float2(o[mt][nt][2] * invHi, o[mt][nt][3] * invHi);
        }
    }
}

// ---------------------------------------------------------------------------
// Launch
// ---------------------------------------------------------------------------
extern "C" void kernel_launch(void* const* d_in, const int* in_sizes, int n_in,
                              void* d_out, int out_size)
{
    const float* x    = (const float*)d_in[0];
    const float* ctx  = (const float*)d_in[1];
    const float* bias = (const float*)d_in[2];
    const float* Wq   = (const float*)d_in[3];
    const float* Wk   = (const float*)d_in[4];
    const float* Wv   = (const float*)d_in[5];
    const float* Wo   = (const float*)d_in[6];
    const float* bo   = (const float*)d_in[7];
    float* out = (float*)d_out;

    cudaFuncSetAttribute(gemm_tc_kernel<0>,
                         cudaFuncAttributeMaxDynamicSharedMemorySize, GEMM_SMEM);
    cudaFuncSetAttribute(gemm_tc_kernel<1>,
                         cudaFuncAttributeMaxDynamicSharedMemorySize, GEMM_SMEM);
    cudaFuncSetAttribute(gemm_tc_kernel<2>,
                         cudaFuncAttributeMaxDynamicSharedMemorySize, GEMM_SMEM);
    cudaFuncSetAttribute(gemm_tc_kernel<3>,
                         cudaFuncAttributeMaxDynamicSharedMemorySize, GEMM_SMEM);
    cudaFuncSetAttribute(attn_kernel,
                         cudaFuncAttributeMaxDynamicSharedMemorySize, ATTN_SMEM);

    float *gQ, *gK, *gV, *gAO;
    cudaGetSymbolAddress((void**)&gQ,  g_Q);
    cudaGetSymbolAddress((void**)&gK,  g_K);
    cudaGetSymbolAddress((void**)&gV,  g_V);
    cudaGetSymbolAddress((void**)&gAO, g_AO);

    dim3 gblk(256);
    gemm_tc_kernel<1><<<dim3(4, (BATCH * NQS) / 128), gblk, GEMM_SMEM>>>(x,   Wq, nullptr, gQ, 0);
    gemm_tc_kernel<2><<<dim3(4, (BATCH * NKS) / 128), gblk, GEMM_SMEM>>>(ctx, Wk, nullptr, gK, 0);
    gemm_tc_kernel<3><<<dim3(4, (BATCH * NKS) / 128), gblk, GEMM_SMEM>>>(ctx, Wv, nullptr, gV, 0);
    attn_kernel<<<dim3(NQS / 128, NHEADS, BATCH), dim3(128), ATTN_SMEM>>>(bias);
    gemm_tc_kernel<0><<<dim3(4, (BATCH * NQS) / 128), gblk, GEMM_SMEM>>>(gAO, Wo, bo, out, 1);
}

// round 6
// speedup vs baseline: 3.9041x; 1.0586x over previous
#include <cuda_runtime.h>
#include <cuda_fp16.h>
#include <cstdint>
#include <math.h>

#define NHEADS 8
#define DH     64
#define BATCH  4
#define NQS    1024
#define NKS    2048
#define DM     512

// Packed fp16 fragment buffers (mma-fragment order); g_AO row-major fp32.
__device__ __half g_Qh[(size_t)BATCH * NQS * DM];
__device__ __half g_Kh[(size_t)BATCH * NKS * DM];
__device__ __half g_Vh[(size_t)BATCH * NKS * DM];
__device__ float  g_AO[(size_t)BATCH * NQS * DM];

// ===========================================================================
// Helpers
// ===========================================================================
__device__ __forceinline__ uint32_t smem_u32(const void* p) {
    uint32_t a;
    asm("{ .reg .u64 t; cvta.to.shared.u64 t, %1; cvt.u32.u64 %0, t; }"
        : "=r"(a) : "l"(p));
    return a;
}
__device__ __forceinline__ uint32_t f2tf32(float f) {
    uint32_t u;
    asm("cvt.rna.tf32.f32 %0, %1;" : "=r"(u) : "f"(f));
    return u;
}
__device__ __forceinline__ void mma_tf32(float c[4], const uint32_t a[4],
                                         uint32_t b0, uint32_t b1) {
    asm volatile(
        "mma.sync.aligned.m16n8k8.row.col.f32.tf32.tf32.f32 "
        "{%0,%1,%2,%3}, {%4,%5,%6,%7}, {%8,%9}, {%0,%1,%2,%3};"
        : "+f"(c[0]), "+f"(c[1]), "+f"(c[2]), "+f"(c[3])
        : "r"(a[0]), "r"(a[1]), "r"(a[2]), "r"(a[3]), "r"(b0), "r"(b1));
}
__device__ __forceinline__ void mma_f16(float c[4], const uint32_t a[4],
                                        uint32_t b0, uint32_t b1) {
    asm volatile(
        "mma.sync.aligned.m16n8k16.row.col.f32.f16.f16.f32 "
        "{%0,%1,%2,%3}, {%4,%5,%6,%7}, {%8,%9}, {%0,%1,%2,%3};"
        : "+f"(c[0]), "+f"(c[1]), "+f"(c[2]), "+f"(c[3])
        : "r"(a[0]), "r"(a[1]), "r"(a[2]), "r"(a[3]), "r"(b0), "r"(b1));
}
__device__ __forceinline__ uint32_t h2u(float lo, float hi) {
    __half2 v = __floats2half2_rn(lo, hi);
    return *(uint32_t*)&v;
}
__device__ __forceinline__ void cp_async16(uint32_t s, const void* g) {
    asm volatile("cp.async.ca.shared.global [%0], [%1], 16;"
                 :: "r"(s), "l"(g) : "memory");
}
__device__ __forceinline__ void cp_commit() {
    asm volatile("cp.async.commit_group;" ::: "memory");
}
template<int N> __device__ __forceinline__ void cp_wait() {
    asm volatile("cp.async.wait_group %0;" :: "n"(N) : "memory");
}

// ===========================================================================
// GEMM: C[M,512] = A[M,512] @ W[512,512]^T.  tf32 mma.sync.
// MODE 0: fp32 store (+bias). MODE 1: Q fp16 A-frag pack (x0.125).
// MODE 2: K fp16 B-frag pack (for S). MODE 3: V fp16 B-frag pack (for PV).
// ===========================================================================
#define GBK    32
#define GPITCH 36
#define GA_BYTES (128 * GPITCH * 4)
#define GSTAGE   (2 * GA_BYTES)
#define GEMM_SMEM (2 * GSTAGE)

template<int MODE>
__global__ __launch_bounds__(256) void gemm_tc_kernel(
    const float* __restrict__ A, const float* __restrict__ W,
    const float* __restrict__ bias, float* __restrict__ C, int addBias)
{
    extern __shared__ char smc[];
    float* sf = (float*)smc;
    const uint32_t sb = smem_u32(smc);

    const int tid  = threadIdx.x;
    const int w    = tid >> 5;
    const int lane = tid & 31;
    const int gid  = lane >> 2;
    const int tig  = lane & 3;
    const int wm   = (w >> 2) * 64;
    const int wn   = (w & 3) * 32;
    const int m0   = blockIdx.y * 128;
    const int n0   = blockIdx.x * 128;

    float acc[4][4][4];
    #pragma unroll
    for (int mt = 0; mt < 4; mt++)
        #pragma unroll
        for (int nt = 0; nt < 4; nt++)
            #pragma unroll
            for (int q = 0; q < 4; q++) acc[mt][nt][q] = 0.f;

    auto stage_load = [&](int buf, int k0) {
        const uint32_t sA = sb + buf * GSTAGE;
        const uint32_t sW = sA + GA_BYTES;
        #pragma unroll
        for (int i = 0; i < 4; i++) {
            int idx = tid + 256 * i;
            int r  = idx >> 3;
            int c4 = (idx & 7) << 2;
            uint32_t off = (uint32_t)(r * GPITCH + c4) * 4u;
            cp_async16(sA + off, A + (size_t)(m0 + r) * DM + k0 + c4);
            cp_async16(sW + off, W + (size_t)(n0 + r) * DM + k0 + c4);
        }
        cp_commit();
    };

    const int NST = DM / GBK;
    stage_load(0, 0);
    stage_load(1, GBK);

    for (int ks = 0; ks < NST; ++ks) {
        const int buf = ks & 1;
        cp_wait<1>();
        __syncthreads();

        const float* As = sf + buf * (GSTAGE / 4);
        const float* Ws = As + (GA_BYTES / 4);

        #pragma unroll
        for (int kk = 0; kk < 4; kk++) {
            const int kb = kk * 8;
            uint32_t af[4][4];
            #pragma unroll
            for (int mt = 0; mt < 4; mt++) {
                int base = (wm + mt * 16 + gid) * GPITCH + kb + tig;
                af[mt][0] = f2tf32(As[base]);
                af[mt][1] = f2tf32(As[base + 8 * GPITCH]);
                af[mt][2] = f2tf32(As[base + 4]);
                af[mt][3] = f2tf32(As[base + 8 * GPITCH + 4]);
            }
            uint32_t bf[4][2];
            #pragma unroll
            for (int nt = 0; nt < 4; nt++) {
                int base = (wn + nt * 8 + gid) * GPITCH + kb + tig;
                bf[nt][0] = f2tf32(Ws[base]);
                bf[nt][1] = f2tf32(Ws[base + 4]);
            }
            #pragma unroll
            for (int mt = 0; mt < 4; mt++)
                #pragma unroll
                for (int nt = 0; nt < 4; nt++)
                    mma_tf32(acc[mt][nt], af[mt], bf[nt][0], bf[nt][1]);
        }
        __syncthreads();
        if (ks + 2 < NST) stage_load(buf, (ks + 2) * GBK);
    }

    // ---------------- epilogue ----------------
    if (MODE == 0) {
        #pragma unroll
        for (int mt = 0; mt < 4; mt++) {
            const int r0 = m0 + wm + mt * 16 + gid;
            #pragma unroll
            for (int nt = 0; nt < 4; nt++) {
                const int col = n0 + wn + nt * 8 + 2 * tig;
                float b0 = 0.f, b1 = 0.f;
                if (addBias) { b0 = bias[col]; b1 = bias[col + 1]; }
                *(float2*)(C + (size_t)r0 * DM + col) =
                    make_float2(acc[mt][nt][0] + b0, acc[mt][nt][1] + b1);
                *(float2*)(C + (size_t)(r0 + 8) * DM + col) =
                    make_float2(acc[mt][nt][2] + b0, acc[mt][nt][3] + b1);
            }
        }
    } else {
        __half* Ch = reinterpret_cast<__half*>(C);
        #pragma unroll
        for (int mt = 0; mt < 4; mt++) {
            #pragma unroll
            for (int nt = 0; nt < 4; nt++) {
                #pragma unroll
                for (int q = 0; q < 4; q++) {
                    const int m   = m0 + wm + mt * 16 + gid + 8 * (q >> 1);
                    const int col = n0 + wn + nt * 8 + 2 * tig + (q & 1);
                    const int h = col >> 6, d = col & 63;
                    float val = acc[mt][nt][q];
                    size_t idx;
                    if (MODE == 1) {
                        // Q: fp16 A-frag (m16k16), pre-scaled by 0.125
                        int b  = m >> 10, qq = m & 1023;
                        int t  = qq >> 4, g = qq & 7, rh = (qq >> 3) & 1;
                        int kk = d >> 4, hi = (d >> 3) & 1;
                        int tq = (d & 7) >> 1, ev = d & 1;
                        idx = ((size_t)((b * 8 + h) * 64 + t) * 4 + kk) * 256
                              + (g * 4 + tq) * 8 + (rh + 2 * hi) * 2 + ev;
                        val *= 0.125f;
                    } else if (MODE == 2) {
                        // K: fp16 B-frag (k16n8) for S = Q K^T
                        int b = m >> 11, n = m & 2047;
                        int kt = n >> 6, ri = n & 63;
                        int nt2 = ri >> 3, g = ri & 7;
                        int kk = d >> 4, hi = (d >> 3) & 1;
                        int t = (d & 7) >> 1, ev = d & 1;
                        idx = (size_t)((b * 32 + kt) * 8 + h) * 4096
                              + (kk * 8 + nt2) * 128 + (g * 4 + t) * 4
                              + hi * 2 + ev;
                    } else {
                        // V: fp16 B-frag (k16n8) for O = P V
                        int b = m >> 11, n = m & 2047;
                        int kt = n >> 6, kr = n & 63;
                        int kk = kr >> 4, hi = (kr >> 3) & 1;
                        int t = (kr & 7) >> 1, ev = kr & 1;
                        int nt2 = d >> 3, g = d & 7;
                        idx = (size_t)((b * 32 + kt) * 8 + h) * 4096
                              + (kk * 8 + nt2) * 128 + (g * 4 + t) * 4
                              + hi * 2 + ev;
                    }
                    Ch[idx] = __float2half_rn(val);
                }
            }
        }
    }
}

// ===========================================================================
// Flash attention, fp16 mma (m16n8k16), f32 accumulate, P kept in registers.
// CTA: 128 q rows x (b,h); 4 warps x 32 rows (two 16-row m-tiles).
// smem (halfs): K[2][4096] | V[2][4096] | Q[8192]  = 48KB.
// ===========================================================================
#define ATTN_SMEM 49152

__global__ __launch_bounds__(128, 3) void attn_kernel(const float* __restrict__ bias)
{
    extern __shared__ __half smh[];
    const uint32_t sb = smem_u32(smh);

    const int tid  = threadIdx.x;
    const int w    = tid >> 5;
    const int lane = tid & 31;
    const int gid  = lane >> 2;
    const int tig  = lane & 3;
    const int q0   = blockIdx.x * 128;
    const int h    = blockIdx.y;
    const int b    = blockIdx.z;

    // Q fragments: CTA-contiguous 16KB
    {
        const __half* gq = g_Qh
            + (size_t)((b * 8 + h) * 64 + blockIdx.x * 8) * 1024;
        #pragma unroll
        for (int i = 0; i < 8; i++) {
            int off = i * 1024 + tid * 8;
            cp_async16(sb + (16384 + off) * 2, gq + off);
        }
    }
    // K/V tile 0 into buffer 0
    {
        const __half* gk = g_Kh + ((size_t)(b * 32 + 0) * 8 + h) * 4096;
        const __half* gv = g_Vh + ((size_t)(b * 32 + 0) * 8 + h) * 4096;
        #pragma unroll
        for (int i = 0; i < 4; i++) {
            int off = i * 1024 + tid * 8;
            cp_async16(sb + off * 2, gk + off);
            cp_async16(sb + (8192 + off) * 2, gv + off);
        }
    }
    cp_commit();

    float o[2][8][4];
    #pragma unroll
    for (int mt = 0; mt < 2; mt++)
        #pragma unroll
        for (int nt = 0; nt < 8; nt++)
            #pragma unroll
            for (int q = 0; q < 4; q++) o[mt][nt][q] = 0.f;
    float mx[2][2] = {{-1e30f, -1e30f}, {-1e30f, -1e30f}};
    float ls[2][2] = {{0.f, 0.f}, {0.f, 0.f}};

    const int qbase = 16384 + w * 2048;

    for (int kb = 0; kb < NKS / 64; kb++) {
        cp_wait<0>();
        __syncthreads();

        // prefetch next K/V into the other buffer (overlaps with compute)
        if (kb + 1 < NKS / 64) {
            const int nb = (kb + 1) & 1;
            const __half* gk = g_Kh + ((size_t)(b * 32 + kb + 1) * 8 + h) * 4096;
            const __half* gv = g_Vh + ((size_t)(b * 32 + kb + 1) * 8 + h) * 4096;
            #pragma unroll
            for (int i = 0; i < 4; i++) {
                int off = i * 1024 + tid * 8;
                cp_async16(sb + (nb * 4096 + off) * 2, gk + off);
                cp_async16(sb + (8192 + nb * 4096 + off) * 2, gv + off);
            }
            cp_commit();
        }

        const int kbo = (kb & 1) * 4096;

        // ---- S = Q K^T ----
        float s[2][8][4];
        #pragma unroll
        for (int mt = 0; mt < 2; mt++)
            #pragma unroll
            for (int nt = 0; nt < 8; nt++)
                #pragma unroll
                for (int q = 0; q < 4; q++) s[mt][nt][q] = 0.f;

        #pragma unroll
        for (int kk = 0; kk < 4; kk++) {
            uint32_t af[2][4];
            #pragma unroll
            for (int mt = 0; mt < 2; mt++) {
                float4 a4 = *(const float4*)&smh[qbase + mt * 1024
                                                 + kk * 256 + lane * 8];
                af[mt][0] = __float_as_uint(a4.x); af[mt][1] = __float_as_uint(a4.y);
                af[mt][2] = __float_as_uint(a4.z); af[mt][3] = __float_as_uint(a4.w);
            }
            #pragma unroll
            for (int nt = 0; nt < 8; nt++) {
                uint2 k2 = *(const uint2*)&smh[kbo + (kk * 8 + nt) * 128 + lane * 4];
                mma_f16(s[0][nt], af[0], k2.x, k2.y);
                mma_f16(s[1][nt], af[1], k2.x, k2.y);
            }
        }

        // ---- + bias, online softmax; overwrite s with P ----
        #pragma unroll
        for (int mt = 0; mt < 2; mt++) {
            const float* bLo = bias
                + ((size_t)b * NQS + q0 + 32 * w + 16 * mt + gid) * NKS + kb * 64;
            const float* bHi = bLo + 8 * (size_t)NKS;

            float rmLo = -1e30f, rmHi = -1e30f;
            #pragma unroll
            for (int nt = 0; nt < 8; nt++) {
                float2 bl = *(const float2*)(bLo + nt * 8 + 2 * tig);
                float2 bh = *(const float2*)(bHi + nt * 8 + 2 * tig);
                s[mt][nt][0] += bl.x;  s[mt][nt][1] += bl.y;
                s[mt][nt][2] += bh.x;  s[mt][nt][3] += bh.y;
                rmLo = fmaxf(rmLo, fmaxf(s[mt][nt][0], s[mt][nt][1]));
                rmHi = fmaxf(rmHi, fmaxf(s[mt][nt][2], s[mt][nt][3]));
            }
            rmLo = fmaxf(rmLo, __shfl_xor_sync(0xffffffffu, rmLo, 1));
            rmLo = fmaxf(rmLo, __shfl_xor_sync(0xffffffffu, rmLo, 2));
            rmHi = fmaxf(rmHi, __shfl_xor_sync(0xffffffffu, rmHi, 1));
            rmHi = fmaxf(rmHi, __shfl_xor_sync(0xffffffffu, rmHi, 2));

            const float mnLo = fmaxf(mx[mt][0], rmLo);
            const float mnHi = fmaxf(mx[mt][1], rmHi);
            const float corrLo = __expf(mx[mt][0] - mnLo);
            const float corrHi = __expf(mx[mt][1] - mnHi);
            mx[mt][0] = mnLo; mx[mt][1] = mnHi;

            float rsLo = 0.f, rsHi = 0.f;
            #pragma unroll
            for (int nt = 0; nt < 8; nt++) {
                float p0 = __expf(s[mt][nt][0] - mnLo);
                float p1 = __expf(s[mt][nt][1] - mnLo);
                float p2 = __expf(s[mt][nt][2] - mnHi);
                float p3 = __expf(s[mt][nt][3] - mnHi);
                rsLo += p0 + p1;
                rsHi += p2 + p3;
                s[mt][nt][0] = p0; s[mt][nt][1] = p1;
                s[mt][nt][2] = p2; s[mt][nt][3] = p3;
                o[mt][nt][0] *= corrLo; o[mt][nt][1] *= corrLo;
                o[mt][nt][2] *= corrHi; o[mt][nt][3] *= corrHi;
            }
            rsLo += __shfl_xor_sync(0xffffffffu, rsLo, 1);
            rsLo += __shfl_xor_sync(0xffffffffu, rsLo, 2);
            rsHi += __shfl_xor_sync(0xffffffffu, rsHi, 1);
            rsHi += __shfl_xor_sync(0xffffffffu, rsHi, 2);
            ls[mt][0] = ls[mt][0] * corrLo + rsLo;
            ls[mt][1] = ls[mt][1] * corrHi + rsHi;
        }

        // ---- O += P V  (P packed register-only: C-frag == fp16 A-frag) ----
        #pragma unroll
        for (int kk = 0; kk < 4; kk++) {
            uint32_t af[2][4];
            #pragma unroll
            for (int mt = 0; mt < 2; mt++) {
                af[mt][0] = h2u(s[mt][2 * kk][0],     s[mt][2 * kk][1]);
                af[mt][1] = h2u(s[mt][2 * kk][2],     s[mt][2 * kk][3]);
                af[mt][2] = h2u(s[mt][2 * kk + 1][0], s[mt][2 * kk + 1][1]);
                af[mt][3] = h2u(s[mt][2 * kk + 1][2], s[mt][2 * kk + 1][3]);
            }
            #pragma unroll
            for (int nt = 0; nt < 8; nt++) {
                uint2 v2 = *(const uint2*)&smh[8192 + kbo
                                               + (kk * 8 + nt) * 128 + lane * 4];
                mma_f16(o[0][nt], af[0], v2.x, v2.y);
                mma_f16(o[1][nt], af[1], v2.x, v2.y);
            }
        }
    }

    // normalize + store (row-major g_AO for the output GEMM)
    #pragma unroll
    for (int mt = 0; mt < 2; mt++) {
        const float invLo = 1.f / ls[mt][0];
        const float invHi = 1.f / ls[mt][1];
        const int rowLo = q0 + 32 * w + 16 * mt + gid;
        float* OgLo = g_AO + ((size_t)b * NQS + rowLo) * DM + h * DH;
        float* OgHi = OgLo + 8 * (size_t)DM;
        #pragma unroll
        for (int nt = 0; nt < 8; nt++) {
            int col = nt * 8 + 2 * tig;
            *(float2*)(OgLo + col) =
                make_float2(o[mt][nt][0] * invLo, o[mt][nt][1] * invLo);
            *(float2*)(OgHi + col) =
                make_float2(o[mt][nt][2] * invHi, o[mt][nt][3] * invHi);
        }
    }
}

// ---------------------------------------------------------------------------
// Launch
// ---------------------------------------------------------------------------
extern "C" void kernel_launch(void* const* d_in, const int* in_sizes, int n_in,
                              void* d_out, int out_size)
{
    const float* x    = (const float*)d_in[0];
    const float* ctx  = (const float*)d_in[1];
    const float* bias = (const float*)d_in[2];
    const float* Wq   = (const float*)d_in[3];
    const float* Wk   = (const float*)d_in[4];
    const float* Wv   = (const float*)d_in[5];
    const float* Wo   = (const float*)d_in[6];
    const float* bo   = (const float*)d_in[7];
    float* out = (float*)d_out;

    cudaFuncSetAttribute(gemm_tc_kernel<0>,
                         cudaFuncAttributeMaxDynamicSharedMemorySize, GEMM_SMEM);
    cudaFuncSetAttribute(gemm_tc_kernel<1>,
                         cudaFuncAttributeMaxDynamicSharedMemorySize, GEMM_SMEM);
    cudaFuncSetAttribute(gemm_tc_kernel<2>,
                         cudaFuncAttributeMaxDynamicSharedMemorySize, GEMM_SMEM);
    cudaFuncSetAttribute(gemm_tc_kernel<3>,
                         cudaFuncAttributeMaxDynamicSharedMemorySize, GEMM_SMEM);
    cudaFuncSetAttribute(attn_kernel,
                         cudaFuncAttributeMaxDynamicSharedMemorySize, ATTN_SMEM);

    void *gQh, *gKh, *gVh;
    float *gAO;
    cudaGetSymbolAddress(&gQh, g_Qh);
    cudaGetSymbolAddress(&gKh, g_Kh);
    cudaGetSymbolAddress(&gVh, g_Vh);
    cudaGetSymbolAddress((void**)&gAO, g_AO);

    dim3 gblk(256);
    gemm_tc_kernel<1><<<dim3(4, (BATCH * NQS) / 128), gblk, GEMM_SMEM>>>(x,   Wq, nullptr, (float*)gQh, 0);
    gemm_tc_kernel<2><<<dim3(4, (BATCH * NKS) / 128), gblk, GEMM_SMEM>>>(ctx, Wk, nullptr, (float*)gKh, 0);
    gemm_tc_kernel<3><<<dim3(4, (BATCH * NKS) / 128), gblk, GEMM_SMEM>>>(ctx, Wv, nullptr, (float*)gVh, 0);
    attn_kernel<<<dim3(NQS / 128, NHEADS, BATCH), dim3(128), ATTN_SMEM>>>(bias);
    gemm_tc_kernel<0><<<dim3(4, (BATCH * NQS) / 128), gblk, GEMM_SMEM>>>(gAO, Wo, bo, out, 1);
}

// round 7
// speedup vs baseline: 3.9764x; 1.0185x over previous
#include <cuda_runtime.h>
#include <cuda_fp16.h>
#include <cstdint>
#include <math.h>

#define NHEADS 8
#define DH     64
#define BATCH  4
#define NQS    1024
#define NKS    2048
#define DM     512

// Packed fp16 fragment buffers (mma-fragment order).
__device__ __half g_Qh[(size_t)BATCH * NQS * DM];
__device__ __half g_Kh[(size_t)BATCH * NKS * DM];
__device__ __half g_Vh[(size_t)BATCH * NKS * DM];
// Split-KV partial outputs (unnormalized) + (m, l) per row per split.
__device__ float  g_AO [(size_t)BATCH * NQS * DM];
__device__ float  g_AO2[(size_t)BATCH * NQS * DM];
__device__ float  g_M[2][BATCH * NHEADS * NQS];
__device__ float  g_L[2][BATCH * NHEADS * NQS];

// ===========================================================================
// Helpers
// ===========================================================================
__device__ __forceinline__ uint32_t smem_u32(const void* p) {
    uint32_t a;
    asm("{ .reg .u64 t; cvta.to.shared.u64 t, %1; cvt.u32.u64 %0, t; }"
        : "=r"(a) : "l"(p));
    return a;
}
__device__ __forceinline__ uint32_t f2tf32(float f) {
    uint32_t u;
    asm("cvt.rna.tf32.f32 %0, %1;" : "=r"(u) : "f"(f));
    return u;
}
__device__ __forceinline__ void mma_tf32(float c[4], const uint32_t a[4],
                                         uint32_t b0, uint32_t b1) {
    asm volatile(
        "mma.sync.aligned.m16n8k8.row.col.f32.tf32.tf32.f32 "
        "{%0,%1,%2,%3}, {%4,%5,%6,%7}, {%8,%9}, {%0,%1,%2,%3};"
        : "+f"(c[0]), "+f"(c[1]), "+f"(c[2]), "+f"(c[3])
        : "r"(a[0]), "r"(a[1]), "r"(a[2]), "r"(a[3]), "r"(b0), "r"(b1));
}
__device__ __forceinline__ void mma_f16(float c[4], const uint32_t a[4],
                                        uint32_t b0, uint32_t b1) {
    asm volatile(
        "mma.sync.aligned.m16n8k16.row.col.f32.f16.f16.f32 "
        "{%0,%1,%2,%3}, {%4,%5,%6,%7}, {%8,%9}, {%0,%1,%2,%3};"
        : "+f"(c[0]), "+f"(c[1]), "+f"(c[2]), "+f"(c[3])
        : "r"(a[0]), "r"(a[1]), "r"(a[2]), "r"(a[3]), "r"(b0), "r"(b1));
}
__device__ __forceinline__ uint32_t h2u(float lo, float hi) {
    __half2 v = __floats2half2_rn(lo, hi);
    return *(uint32_t*)&v;
}
__device__ __forceinline__ void cp_async16(uint32_t s, const void* g) {
    asm volatile("cp.async.ca.shared.global [%0], [%1], 16;"
                 :: "r"(s), "l"(g) : "memory");
}
__device__ __forceinline__ void cp_commit() {
    asm volatile("cp.async.commit_group;" ::: "memory");
}
template<int N> __device__ __forceinline__ void cp_wait() {
    asm volatile("cp.async.wait_group %0;" :: "n"(N) : "memory");
}

// ===========================================================================
// GEMM: C[M,512] = A[M,512] @ W[512,512]^T.  tf32 mma.sync.
// MODE 0: fp32 store (+bias). MODE 1: Q fp16 A-frag pack (x0.125).
// MODE 2: K fp16 B-frag pack (for S). MODE 3: V fp16 B-frag pack (for PV).
// ===========================================================================
#define GBK    32
#define GPITCH 36
#define GA_BYTES (128 * GPITCH * 4)
#define GSTAGE   (2 * GA_BYTES)
#define GEMM_SMEM (2 * GSTAGE)

template<int MODE>
__global__ __launch_bounds__(256) void gemm_tc_kernel(
    const float* __restrict__ A, const float* __restrict__ W,
    const float* __restrict__ bias, float* __restrict__ C, int addBias)
{
    extern __shared__ char smc[];
    float* sf = (float*)smc;
    const uint32_t sb = smem_u32(smc);

    const int tid  = threadIdx.x;
    const int w    = tid >> 5;
    const int lane = tid & 31;
    const int gid  = lane >> 2;
    const int tig  = lane & 3;
    const int wm   = (w >> 2) * 64;
    const int wn   = (w & 3) * 32;
    const int m0   = blockIdx.y * 128;
    const int n0   = blockIdx.x * 128;

    float acc[4][4][4];
    #pragma unroll
    for (int mt = 0; mt < 4; mt++)
        #pragma unroll
        for (int nt = 0; nt < 4; nt++)
            #pragma unroll
            for (int q = 0; q < 4; q++) acc[mt][nt][q] = 0.f;

    auto stage_load = [&](int buf, int k0) {
        const uint32_t sA = sb + buf * GSTAGE;
        const uint32_t sW = sA + GA_BYTES;
        #pragma unroll
        for (int i = 0; i < 4; i++) {
            int idx = tid + 256 * i;
            int r  = idx >> 3;
            int c4 = (idx & 7) << 2;
            uint32_t off = (uint32_t)(r * GPITCH + c4) * 4u;
            cp_async16(sA + off, A + (size_t)(m0 + r) * DM + k0 + c4);
            cp_async16(sW + off, W + (size_t)(n0 + r) * DM + k0 + c4);
        }
        cp_commit();
    };

    const int NST = DM / GBK;
    stage_load(0, 0);
    stage_load(1, GBK);

    for (int ks = 0; ks < NST; ++ks) {
        const int buf = ks & 1;
        cp_wait<1>();
        __syncthreads();

        const float* As = sf + buf * (GSTAGE / 4);
        const float* Ws = As + (GA_BYTES / 4);

        #pragma unroll
        for (int kk = 0; kk < 4; kk++) {
            const int kb = kk * 8;
            uint32_t af[4][4];
            #pragma unroll
            for (int mt = 0; mt < 4; mt++) {
                int base = (wm + mt * 16 + gid) * GPITCH + kb + tig;
                af[mt][0] = f2tf32(As[base]);
                af[mt][1] = f2tf32(As[base + 8 * GPITCH]);
                af[mt][2] = f2tf32(As[base + 4]);
                af[mt][3] = f2tf32(As[base + 8 * GPITCH + 4]);
            }
            uint32_t bf[4][2];
            #pragma unroll
            for (int nt = 0; nt < 4; nt++) {
                int base = (wn + nt * 8 + gid) * GPITCH + kb + tig;
                bf[nt][0] = f2tf32(Ws[base]);
                bf[nt][1] = f2tf32(Ws[base + 4]);
            }
            #pragma unroll
            for (int mt = 0; mt < 4; mt++)
                #pragma unroll
                for (int nt = 0; nt < 4; nt++)
                    mma_tf32(acc[mt][nt], af[mt], bf[nt][0], bf[nt][1]);
        }
        __syncthreads();
        if (ks + 2 < NST) stage_load(buf, (ks + 2) * GBK);
    }

    // ---------------- epilogue ----------------
    if (MODE == 0) {
        #pragma unroll
        for (int mt = 0; mt < 4; mt++) {
            const int r0 = m0 + wm + mt * 16 + gid;
            #pragma unroll
            for (int nt = 0; nt < 4; nt++) {
                const int col = n0 + wn + nt * 8 + 2 * tig;
                float b0 = 0.f, b1 = 0.f;
                if (addBias) { b0 = bias[col]; b1 = bias[col + 1]; }
                *(float2*)(C + (size_t)r0 * DM + col) =
                    make_float2(acc[mt][nt][0] + b0, acc[mt][nt][1] + b1);
                *(float2*)(C + (size_t)(r0 + 8) * DM + col) =
                    make_float2(acc[mt][nt][2] + b0, acc[mt][nt][3] + b1);
            }
        }
    } else {
        __half* Ch = reinterpret_cast<__half*>(C);
        #pragma unroll
        for (int mt = 0; mt < 4; mt++) {
            #pragma unroll
            for (int nt = 0; nt < 4; nt++) {
                #pragma unroll
                for (int q = 0; q < 4; q++) {
                    const int m   = m0 + wm + mt * 16 + gid + 8 * (q >> 1);
                    const int col = n0 + wn + nt * 8 + 2 * tig + (q & 1);
                    const int h = col >> 6, d = col & 63;
                    float val = acc[mt][nt][q];
                    size_t idx;
                    if (MODE == 1) {
                        // Q: fp16 A-frag (m16k16), pre-scaled by 0.125
                        int b  = m >> 10, qq = m & 1023;
                        int t  = qq >> 4, g = qq & 7, rh = (qq >> 3) & 1;
                        int kk = d >> 4, hi = (d >> 3) & 1;
                        int tq = (d & 7) >> 1, ev = d & 1;
                        idx = ((size_t)((b * 8 + h) * 64 + t) * 4 + kk) * 256
                              + (g * 4 + tq) * 8 + (rh + 2 * hi) * 2 + ev;
                        val *= 0.125f;
                    } else if (MODE == 2) {
                        // K: fp16 B-frag (k16n8) for S = Q K^T
                        int b = m >> 11, n = m & 2047;
                        int kt = n >> 6, ri = n & 63;
                        int nt2 = ri >> 3, g = ri & 7;
                        int kk = d >> 4, hi = (d >> 3) & 1;
                        int t = (d & 7) >> 1, ev = d & 1;
                        idx = (size_t)((b * 32 + kt) * 8 + h) * 4096
                              + (kk * 8 + nt2) * 128 + (g * 4 + t) * 4
                              + hi * 2 + ev;
                    } else {
                        // V: fp16 B-frag (k16n8) for O = P V
                        int b = m >> 11, n = m & 2047;
                        int kt = n >> 6, kr = n & 63;
                        int kk = kr >> 4, hi = (kr >> 3) & 1;
                        int t = (kr & 7) >> 1, ev = kr & 1;
                        int nt2 = d >> 3, g = d & 7;
                        idx = (size_t)((b * 32 + kt) * 8 + h) * 4096
                              + (kk * 8 + nt2) * 128 + (g * 4 + t) * 4
                              + hi * 2 + ev;
                    }
                    Ch[idx] = __float2half_rn(val);
                }
            }
        }
    }
}

// ===========================================================================
// Flash attention, fp16 mma, f32 accumulate, P in registers, SPLIT-KV x2.
// Grid (16, 8, 4): blockIdx.x = qtile*2 + split; each CTA does 16 KV tiles.
// CTA: 128 q rows, 4 warps x 32 rows. Writes unnormalized O + (m,l).
// smem (halfs): K[2][4096] | V[2][4096] | Q[8192]  = 48KB.
// ===========================================================================
#define ATTN_SMEM 49152
#define KV_SPLIT_TILES 16

__global__ __launch_bounds__(128, 3) void attn_kernel(const float* __restrict__ bias)
{
    extern __shared__ __half smh[];
    const uint32_t sb = smem_u32(smh);

    const int tid   = threadIdx.x;
    const int w     = tid >> 5;
    const int lane  = tid & 31;
    const int gid   = lane >> 2;
    const int tig   = lane & 3;
    const int split = blockIdx.x & 1;
    const int qt    = blockIdx.x >> 1;
    const int q0    = qt * 128;
    const int h     = blockIdx.y;
    const int b     = blockIdx.z;
    const int kb0   = split * KV_SPLIT_TILES;

    // Q fragments: CTA-contiguous 16KB
    {
        const __half* gq = g_Qh + (size_t)((b * 8 + h) * 64 + qt * 8) * 1024;
        #pragma unroll
        for (int i = 0; i < 8; i++) {
            int off = i * 1024 + tid * 8;
            cp_async16(sb + (16384 + off) * 2, gq + off);
        }
    }
    // first K/V tile
    {
        const __half* gk = g_Kh + ((size_t)(b * 32 + kb0) * 8 + h) * 4096;
        const __half* gv = g_Vh + ((size_t)(b * 32 + kb0) * 8 + h) * 4096;
        #pragma unroll
        for (int i = 0; i < 4; i++) {
            int off = i * 1024 + tid * 8;
            cp_async16(sb + ((kb0 & 1) * 4096 + off) * 2, gk + off);
            cp_async16(sb + (8192 + (kb0 & 1) * 4096 + off) * 2, gv + off);
        }
    }
    cp_commit();

    float o[2][8][4];
    #pragma unroll
    for (int mt = 0; mt < 2; mt++)
        #pragma unroll
        for (int nt = 0; nt < 8; nt++)
            #pragma unroll
            for (int q = 0; q < 4; q++) o[mt][nt][q] = 0.f;
    float mx[2][2] = {{-1e30f, -1e30f}, {-1e30f, -1e30f}};
    float ls[2][2] = {{0.f, 0.f}, {0.f, 0.f}};

    const int qbase = 16384 + w * 2048;

    for (int kb = kb0; kb < kb0 + KV_SPLIT_TILES; kb++) {
        cp_wait<0>();
        __syncthreads();

        if (kb + 1 < kb0 + KV_SPLIT_TILES) {
            const int nb = (kb + 1) & 1;
            const __half* gk = g_Kh + ((size_t)(b * 32 + kb + 1) * 8 + h) * 4096;
            const __half* gv = g_Vh + ((size_t)(b * 32 + kb + 1) * 8 + h) * 4096;
            #pragma unroll
            for (int i = 0; i < 4; i++) {
                int off = i * 1024 + tid * 8;
                cp_async16(sb + (nb * 4096 + off) * 2, gk + off);
                cp_async16(sb + (8192 + nb * 4096 + off) * 2, gv + off);
            }
            cp_commit();
        }

        const int kbo = (kb & 1) * 4096;

        // ---- S = Q K^T ----
        float s[2][8][4];
        #pragma unroll
        for (int mt = 0; mt < 2; mt++)
            #pragma unroll
            for (int nt = 0; nt < 8; nt++)
                #pragma unroll
                for (int q = 0; q < 4; q++) s[mt][nt][q] = 0.f;

        #pragma unroll
        for (int kk = 0; kk < 4; kk++) {
            uint32_t af[2][4];
            #pragma unroll
            for (int mt = 0; mt < 2; mt++) {
                float4 a4 = *(const float4*)&smh[qbase + mt * 1024
                                                 + kk * 256 + lane * 8];
                af[mt][0] = __float_as_uint(a4.x); af[mt][1] = __float_as_uint(a4.y);
                af[mt][2] = __float_as_uint(a4.z); af[mt][3] = __float_as_uint(a4.w);
            }
            #pragma unroll
            for (int nt = 0; nt < 8; nt++) {
                uint2 k2 = *(const uint2*)&smh[kbo + (kk * 8 + nt) * 128 + lane * 4];
                mma_f16(s[0][nt], af[0], k2.x, k2.y);
                mma_f16(s[1][nt], af[1], k2.x, k2.y);
            }
        }

        // ---- + bias, online softmax; overwrite s with P ----
        #pragma unroll
        for (int mt = 0; mt < 2; mt++) {
            const float* bLo = bias
                + ((size_t)b * NQS + q0 + 32 * w + 16 * mt + gid) * NKS + kb * 64;
            const float* bHi = bLo + 8 * (size_t)NKS;

            float rmLo = -1e30f, rmHi = -1e30f;
            #pragma unroll
            for (int nt = 0; nt < 8; nt++) {
                float2 bl = *(const float2*)(bLo + nt * 8 + 2 * tig);
                float2 bh = *(const float2*)(bHi + nt * 8 + 2 * tig);
                s[mt][nt][0] += bl.x;  s[mt][nt][1] += bl.y;
                s[mt][nt][2] += bh.x;  s[mt][nt][3] += bh.y;
                rmLo = fmaxf(rmLo, fmaxf(s[mt][nt][0], s[mt][nt][1]));
                rmHi = fmaxf(rmHi, fmaxf(s[mt][nt][2], s[mt][nt][3]));
            }
            rmLo = fmaxf(rmLo, __shfl_xor_sync(0xffffffffu, rmLo, 1));
            rmLo = fmaxf(rmLo, __shfl_xor_sync(0xffffffffu, rmLo, 2));
            rmHi = fmaxf(rmHi, __shfl_xor_sync(0xffffffffu, rmHi, 1));
            rmHi = fmaxf(rmHi, __shfl_xor_sync(0xffffffffu, rmHi, 2));

            const float mnLo = fmaxf(mx[mt][0], rmLo);
            const float mnHi = fmaxf(mx[mt][1], rmHi);
            const float corrLo = __expf(mx[mt][0] - mnLo);
            const float corrHi = __expf(mx[mt][1] - mnHi);
            mx[mt][0] = mnLo; mx[mt][1] = mnHi;

            float rsLo = 0.f, rsHi = 0.f;
            #pragma unroll
            for (int nt = 0; nt < 8; nt++) {
                float p0 = __expf(s[mt][nt][0] - mnLo);
                float p1 = __expf(s[mt][nt][1] - mnLo);
                float p2 = __expf(s[mt][nt][2] - mnHi);
                float p3 = __expf(s[mt][nt][3] - mnHi);
                rsLo += p0 + p1;
                rsHi += p2 + p3;
                s[mt][nt][0] = p0; s[mt][nt][1] = p1;
                s[mt][nt][2] = p2; s[mt][nt][3] = p3;
                o[mt][nt][0] *= corrLo; o[mt][nt][1] *= corrLo;
                o[mt][nt][2] *= corrHi; o[mt][nt][3] *= corrHi;
            }
            rsLo += __shfl_xor_sync(0xffffffffu, rsLo, 1);
            rsLo += __shfl_xor_sync(0xffffffffu, rsLo, 2);
            rsHi += __shfl_xor_sync(0xffffffffu, rsHi, 1);
            rsHi += __shfl_xor_sync(0xffffffffu, rsHi, 2);
            ls[mt][0] = ls[mt][0] * corrLo + rsLo;
            ls[mt][1] = ls[mt][1] * corrHi + rsHi;
        }

        // ---- O += P V  (C-frag == fp16 A-frag; register-only) ----
        #pragma unroll
        for (int kk = 0; kk < 4; kk++) {
            uint32_t af[2][4];
            #pragma unroll
            for (int mt = 0; mt < 2; mt++) {
                af[mt][0] = h2u(s[mt][2 * kk][0],     s[mt][2 * kk][1]);
                af[mt][1] = h2u(s[mt][2 * kk][2],     s[mt][2 * kk][3]);
                af[mt][2] = h2u(s[mt][2 * kk + 1][0], s[mt][2 * kk + 1][1]);
                af[mt][3] = h2u(s[mt][2 * kk + 1][2], s[mt][2 * kk + 1][3]);
            }
            #pragma unroll
            for (int nt = 0; nt < 8; nt++) {
                uint2 v2 = *(const uint2*)&smh[8192 + kbo
                                               + (kk * 8 + nt) * 128 + lane * 4];
                mma_f16(o[0][nt], af[0], v2.x, v2.y);
                mma_f16(o[1][nt], af[1], v2.x, v2.y);
            }
        }
    }

    // store unnormalized partials + (m, l)
    float* Opart = split ? g_AO2 : g_AO;
    #pragma unroll
    for (int mt = 0; mt < 2; mt++) {
        const int rowLo = q0 + 32 * w + 16 * mt + gid;
        float* OgLo = Opart + ((size_t)b * NQS + rowLo) * DM + h * DH;
        float* OgHi = OgLo + 8 * (size_t)DM;
        #pragma unroll
        for (int nt = 0; nt < 8; nt++) {
            int col = nt * 8 + 2 * tig;
            *(float2*)(OgLo + col) = make_float2(o[mt][nt][0], o[mt][nt][1]);
            *(float2*)(OgHi + col) = make_float2(o[mt][nt][2], o[mt][nt][3]);
        }
        if (tig == 0) {
            int mi = (b * 8 + h) * 1024 + rowLo;
            g_M[split][mi]     = mx[mt][0];
            g_L[split][mi]     = ls[mt][0];
            g_M[split][mi + 8] = mx[mt][1];
            g_L[split][mi + 8] = ls[mt][1];
        }
    }
}

// ===========================================================================
// Merge the two KV splits: O = (O0*e^{m0-m*} + O1*e^{m1-m*}) / l*
// One thread per float2 of the output. Writes merged result into g_AO.
// ===========================================================================
__global__ __launch_bounds__(256) void merge_kernel()
{
    const size_t i = (size_t)blockIdx.x * 256 + threadIdx.x;   // per float2
    const size_t e = i * 2;
    const size_t row = e / DM;                 // b*NQS + q
    const int d  = (int)(e % DM);
    const int b  = (int)(row >> 10);
    const int q  = (int)(row & 1023);
    const int h  = d >> 6;
    const int mi = (b * 8 + h) * 1024 + q;

    const float m0 = g_M[0][mi], m1 = g_M[1][mi];
    const float l0 = g_L[0][mi], l1 = g_L[1][mi];
    const float ms = fmaxf(m0, m1);
    const float a0 = __expf(m0 - ms), a1 = __expf(m1 - ms);
    const float inv = 1.f / (l0 * a0 + l1 * a1);

    const float2 o0 = *(const float2*)&g_AO [e];
    const float2 o1 = *(const float2*)&g_AO2[e];
    *(float2*)&g_AO[e] = make_float2((o0.x * a0 + o1.x * a1) * inv,
                                     (o0.y * a0 + o1.y * a1) * inv);
}

// ---------------------------------------------------------------------------
// Launch
// ---------------------------------------------------------------------------
extern "C" void kernel_launch(void* const* d_in, const int* in_sizes, int n_in,
                              void* d_out, int out_size)
{
    const float* x    = (const float*)d_in[0];
    const float* ctx  = (const float*)d_in[1];
    const float* bias = (const float*)d_in[2];
    const float* Wq   = (const float*)d_in[3];
    const float* Wk   = (const float*)d_in[4];
    const float* Wv   = (const float*)d_in[5];
    const float* Wo   = (const float*)d_in[6];
    const float* bo   = (const float*)d_in[7];
    float* out = (float*)d_out;

    cudaFuncSetAttribute(gemm_tc_kernel<0>,
                         cudaFuncAttributeMaxDynamicSharedMemorySize, GEMM_SMEM);
    cudaFuncSetAttribute(gemm_tc_kernel<1>,
                         cudaFuncAttributeMaxDynamicSharedMemorySize, GEMM_SMEM);
    cudaFuncSetAttribute(gemm_tc_kernel<2>,
                         cudaFuncAttributeMaxDynamicSharedMemorySize, GEMM_SMEM);
    cudaFuncSetAttribute(gemm_tc_kernel<3>,
                         cudaFuncAttributeMaxDynamicSharedMemorySize, GEMM_SMEM);
    cudaFuncSetAttribute(attn_kernel,
                         cudaFuncAttributeMaxDynamicSharedMemorySize, ATTN_SMEM);

    void *gQh, *gKh, *gVh;
    float *gAO;
    cudaGetSymbolAddress(&gQh, g_Qh);
    cudaGetSymbolAddress(&gKh, g_Kh);
    cudaGetSymbolAddress(&gVh, g_Vh);
    cudaGetSymbolAddress((void**)&gAO, g_AO);

    dim3 gblk(256);
    gemm_tc_kernel<1><<<dim3(4, (BATCH * NQS) / 128), gblk, GEMM_SMEM>>>(x,   Wq, nullptr, (float*)gQh, 0);
    gemm_tc_kernel<2><<<dim3(4, (BATCH * NKS) / 128), gblk, GEMM_SMEM>>>(ctx, Wk, nullptr, (float*)gKh, 0);
    gemm_tc_kernel<3><<<dim3(4, (BATCH * NKS) / 128), gblk, GEMM_SMEM>>>(ctx, Wv, nullptr, (float*)gVh, 0);
    attn_kernel<<<dim3((NQS / 128) * 2, NHEADS, BATCH), dim3(128), ATTN_SMEM>>>(bias);
    merge_kernel<<<(BATCH * NQS * DM / 2) / 256, 256>>>();
    gemm_tc_kernel<0><<<dim3(4, (BATCH * NQS) / 128), gblk, GEMM_SMEM>>>(gAO, Wo, bo, out, 1);
}

// round 8
// speedup vs baseline: 4.4652x; 1.1229x over previous
#include <cuda_runtime.h>
#include <cuda_fp16.h>
#include <cstdint>
#include <math.h>

#define NHEADS 8
#define DH     64
#define BATCH  4
#define NQS    1024
#define NKS    2048
#define DM     512

// fp16 copies of inputs (converted once per run).
__device__ __half g_Xh  [(size_t)BATCH * NQS * DM];
__device__ __half g_Ctxh[(size_t)BATCH * NKS * DM];
__device__ __half g_Wqh[DM * DM];
__device__ __half g_Wkh[DM * DM];
__device__ __half g_Wvh[DM * DM];
__device__ __half g_Woh[DM * DM];
// Packed fp16 fragment buffers (mma-fragment order).
__device__ __half g_Qh[(size_t)BATCH * NQS * DM];
__device__ __half g_Kh[(size_t)BATCH * NKS * DM];
__device__ __half g_Vh[(size_t)BATCH * NKS * DM];
// Split-KV partial outputs (unnormalized, fp32) + (m, l) per row per split.
__device__ float  g_AO [(size_t)BATCH * NQS * DM];
__device__ float  g_AO2[(size_t)BATCH * NQS * DM];
__device__ float  g_M[2][BATCH * NHEADS * NQS];
__device__ float  g_L[2][BATCH * NHEADS * NQS];
// Merged attention output in fp16 (A operand of the output GEMM).
__device__ __half g_AOh[(size_t)BATCH * NQS * DM];

// ===========================================================================
// Helpers
// ===========================================================================
__device__ __forceinline__ uint32_t smem_u32(const void* p) {
    uint32_t a;
    asm("{ .reg .u64 t; cvta.to.shared.u64 t, %1; cvt.u32.u64 %0, t; }"
        : "=r"(a) : "l"(p));
    return a;
}
__device__ __forceinline__ void mma_f16(float c[4], const uint32_t a[4],
                                        uint32_t b0, uint32_t b1) {
    asm volatile(
        "mma.sync.aligned.m16n8k16.row.col.f32.f16.f16.f32 "
        "{%0,%1,%2,%3}, {%4,%5,%6,%7}, {%8,%9}, {%0,%1,%2,%3};"
        : "+f"(c[0]), "+f"(c[1]), "+f"(c[2]), "+f"(c[3])
        : "r"(a[0]), "r"(a[1]), "r"(a[2]), "r"(a[3]), "r"(b0), "r"(b1));
}
__device__ __forceinline__ void ldsm_x4(uint32_t r[4], uint32_t addr) {
    asm volatile("ldmatrix.sync.aligned.m8n8.x4.shared.b16 {%0,%1,%2,%3}, [%4];"
                 : "=r"(r[0]), "=r"(r[1]), "=r"(r[2]), "=r"(r[3]) : "r"(addr));
}
__device__ __forceinline__ void ldsm_x2(uint32_t r[2], uint32_t addr) {
    asm volatile("ldmatrix.sync.aligned.m8n8.x2.shared.b16 {%0,%1}, [%2];"
                 : "=r"(r[0]), "=r"(r[1]) : "r"(addr));
}
__device__ __forceinline__ uint32_t h2u(float lo, float hi) {
    __half2 v = __floats2half2_rn(lo, hi);
    return *(uint32_t*)&v;
}
__device__ __forceinline__ void cp_async16(uint32_t s, const void* g) {
    asm volatile("cp.async.ca.shared.global [%0], [%1], 16;"
                 :: "r"(s), "l"(g) : "memory");
}
__device__ __forceinline__ void cp_commit() {
    asm volatile("cp.async.commit_group;" ::: "memory");
}
template<int N> __device__ __forceinline__ void cp_wait() {
    asm volatile("cp.async.wait_group %0;" :: "n"(N) : "memory");
}

// ===========================================================================
// fp32 -> fp16 conversion (n4 = element count / 4)
// ===========================================================================
__global__ __launch_bounds__(256) void f32to16_kernel(
    const float* __restrict__ src, __half* __restrict__ dst, int n4)
{
    int i = blockIdx.x * 256 + threadIdx.x;
    if (i < n4) {
        float4 v = ((const float4*)src)[i];
        *(uint2*)&dst[(size_t)i * 4] =
            make_uint2(h2u(v.x, v.y), h2u(v.z, v.w));
    }
}

// ===========================================================================
// GEMM: C[M,512] = A[M,512] @ W[512,512]^T.  fp16 mma (m16n8k16), f32 accum.
// CTA 128x128, BK=32 halves, cp.async double buffer, 8 warps (2m x 4n),
// warp 64x32, ldmatrix fragment loads, smem pitch 40 halves (bank-clean).
// MODE 0: fp32 store (+bias). MODE 1: Q A-frag pack (x0.125).
// MODE 2: K B-frag pack. MODE 3: V B-frag pack.
// ===========================================================================
#define GBKH    32
#define GPITCHH 40
#define GTILEH  (128 * GPITCHH)          // 5120 halves
#define GEMM_SMEM (4 * GTILEH * 2)       // 40960 bytes

template<int MODE>
__global__ __launch_bounds__(256, 2) void gemm_h_kernel(
    const __half* __restrict__ A, const __half* __restrict__ W,
    const float* __restrict__ bias, float* __restrict__ C, int addBias)
{
    extern __shared__ __half smh[];
    const uint32_t sb = smem_u32(smh);

    const int tid  = threadIdx.x;
    const int w    = tid >> 5;
    const int lane = tid & 31;
    const int gid  = lane >> 2;
    const int tig  = lane & 3;
    const int wm   = (w >> 2) * 64;
    const int wn   = (w & 3) * 32;
    const int m0   = blockIdx.y * 128;
    const int n0   = blockIdx.x * 128;

    float acc[4][4][4];
    #pragma unroll
    for (int mt = 0; mt < 4; mt++)
        #pragma unroll
        for (int nt = 0; nt < 4; nt++)
            #pragma unroll
            for (int q = 0; q < 4; q++) acc[mt][nt][q] = 0.f;

    auto stage_load = [&](int buf, int ks) {
        const int k0 = ks * GBKH;
        const uint32_t sA = sb + (uint32_t)(buf * GTILEH) * 2u;
        const uint32_t sW = sb + (uint32_t)(2 * GTILEH + buf * GTILEH) * 2u;
        #pragma unroll
        for (int i = 0; i < 2; i++) {
            int idx = tid + 256 * i;          // 0..511
            int r   = idx >> 2;               // 0..127
            int c   = (idx & 3) * 8;          // half-chunk
            cp_async16(sA + (uint32_t)(r * GPITCHH + c) * 2u,
                       A + (size_t)(m0 + r) * DM + k0 + c);
            cp_async16(sW + (uint32_t)(r * GPITCHH + c) * 2u,
                       W + (size_t)(n0 + r) * DM + k0 + c);
        }
        cp_commit();
    };

    const int NST = DM / GBKH;   // 16
    stage_load(0, 0);
    stage_load(1, 1);

    // lane-dependent ldmatrix offsets (halves)
    const int aRow = ((lane >> 3) & 1) * 8 + (lane & 7);
    const int aK   = ((lane >> 4) & 1) * 8;
    const int bRow = lane & 7;
    const int bK   = ((lane >> 3) & 1) * 8;

    for (int ks = 0; ks < NST; ++ks) {
        cp_wait<1>();
        __syncthreads();

        const uint32_t aBase = sb + (uint32_t)((ks & 1) * GTILEH) * 2u;
        const uint32_t bBase = sb + (uint32_t)(2 * GTILEH + (ks & 1) * GTILEH) * 2u;

        #pragma unroll
        for (int kst = 0; kst < 2; kst++) {
            uint32_t af[4][4];
            #pragma unroll
            for (int mt = 0; mt < 4; mt++)
                ldsm_x4(af[mt], aBase
                        + (uint32_t)((wm + mt * 16 + aRow) * GPITCHH
                                     + kst * 16 + aK) * 2u);
            uint32_t bf[4][2];
            #pragma unroll
            for (int nt = 0; nt < 4; nt++)
                ldsm_x2(bf[nt], bBase
                        + (uint32_t)((wn + nt * 8 + bRow) * GPITCHH
                                     + kst * 16 + bK) * 2u);
            #pragma unroll
            for (int mt = 0; mt < 4; mt++)
                #pragma unroll
                for (int nt = 0; nt < 4; nt++)
                    mma_f16(acc[mt][nt], af[mt], bf[nt][0], bf[nt][1]);
        }
        __syncthreads();
        if (ks + 2 < NST) stage_load(ks & 1, ks + 2);
    }

    // ---------------- epilogue ----------------
    if (MODE == 0) {
        #pragma unroll
        for (int mt = 0; mt < 4; mt++) {
            const int r0 = m0 + wm + mt * 16 + gid;
            #pragma unroll
            for (int nt = 0; nt < 4; nt++) {
                const int col = n0 + wn + nt * 8 + 2 * tig;
                float b0 = 0.f, b1 = 0.f;
                if (addBias) { b0 = bias[col]; b1 = bias[col + 1]; }
                *(float2*)(C + (size_t)r0 * DM + col) =
                    make_float2(acc[mt][nt][0] + b0, acc[mt][nt][1] + b1);
                *(float2*)(C + (size_t)(r0 + 8) * DM + col) =
                    make_float2(acc[mt][nt][2] + b0, acc[mt][nt][3] + b1);
            }
        }
    } else {
        __half* Ch = reinterpret_cast<__half*>(C);
        #pragma unroll
        for (int mt = 0; mt < 4; mt++) {
            #pragma unroll
            for (int nt = 0; nt < 4; nt++) {
                #pragma unroll
                for (int q = 0; q < 4; q++) {
                    const int m   = m0 + wm + mt * 16 + gid + 8 * (q >> 1);
                    const int col = n0 + wn + nt * 8 + 2 * tig + (q & 1);
                    const int h = col >> 6, d = col & 63;
                    float val = acc[mt][nt][q];
                    size_t idx;
                    if (MODE == 1) {
                        // Q: fp16 A-frag (m16k16), pre-scaled by 0.125
                        int b  = m >> 10, qq = m & 1023;
                        int t  = qq >> 4, g = qq & 7, rh = (qq >> 3) & 1;
                        int kk = d >> 4, hi = (d >> 3) & 1;
                        int tq = (d & 7) >> 1, ev = d & 1;
                        idx = ((size_t)((b * 8 + h) * 64 + t) * 4 + kk) * 256
                              + (g * 4 + tq) * 8 + (rh + 2 * hi) * 2 + ev;
                        val *= 0.125f;
                    } else if (MODE == 2) {
                        // K: fp16 B-frag (k16n8) for S = Q K^T
                        int b = m >> 11, n = m & 2047;
                        int kt = n >> 6, ri = n & 63;
                        int nt2 = ri >> 3, g = ri & 7;
                        int kk = d >> 4, hi = (d >> 3) & 1;
                        int t = (d & 7) >> 1, ev = d & 1;
                        idx = (size_t)((b * 32 + kt) * 8 + h) * 4096
                              + (kk * 8 + nt2) * 128 + (g * 4 + t) * 4
                              + hi * 2 + ev;
                    } else {
                        // V: fp16 B-frag (k16n8) for O = P V
                        int b = m >> 11, n = m & 2047;
                        int kt = n >> 6, kr = n & 63;
                        int kk = kr >> 4, hi = (kr >> 3) & 1;
                        int t = (kr & 7) >> 1, ev = kr & 1;
                        int nt2 = d >> 3, g = d & 7;
                        idx = (size_t)((b * 32 + kt) * 8 + h) * 4096
                              + (kk * 8 + nt2) * 128 + (g * 4 + t) * 4
                              + hi * 2 + ev;
                    }
                    Ch[idx] = __float2half_rn(val);
                }
            }
        }
    }
}

// ===========================================================================
// Flash attention, fp16 mma, f32 accumulate, P in registers, SPLIT-KV x2.
// (unchanged from R7)
// ===========================================================================
#define ATTN_SMEM 49152
#define KV_SPLIT_TILES 16

__global__ __launch_bounds__(128, 3) void attn_kernel(const float* __restrict__ bias)
{
    extern __shared__ __half smha[];
    const uint32_t sb = smem_u32(smha);

    const int tid   = threadIdx.x;
    const int w     = tid >> 5;
    const int lane  = tid & 31;
    const int gid   = lane >> 2;
    const int tig   = lane & 3;
    const int split = blockIdx.x & 1;
    const int qt    = blockIdx.x >> 1;
    const int q0    = qt * 128;
    const int h     = blockIdx.y;
    const int b     = blockIdx.z;
    const int kb0   = split * KV_SPLIT_TILES;

    {
        const __half* gq = g_Qh + (size_t)((b * 8 + h) * 64 + qt * 8) * 1024;
        #pragma unroll
        for (int i = 0; i < 8; i++) {
            int off = i * 1024 + tid * 8;
            cp_async16(sb + (16384 + off) * 2, gq + off);
        }
    }
    {
        const __half* gk = g_Kh + ((size_t)(b * 32 + kb0) * 8 + h) * 4096;
        const __half* gv = g_Vh + ((size_t)(b * 32 + kb0) * 8 + h) * 4096;
        #pragma unroll
        for (int i = 0; i < 4; i++) {
            int off = i * 1024 + tid * 8;
            cp_async16(sb + ((kb0 & 1) * 4096 + off) * 2, gk + off);
            cp_async16(sb + (8192 + (kb0 & 1) * 4096 + off) * 2, gv + off);
        }
    }
    cp_commit();

    float o[2][8][4];
    #pragma unroll
    for (int mt = 0; mt < 2; mt++)
        #pragma unroll
        for (int nt = 0; nt < 8; nt++)
            #pragma unroll
            for (int q = 0; q < 4; q++) o[mt][nt][q] = 0.f;
    float mx[2][2] = {{-1e30f, -1e30f}, {-1e30f, -1e30f}};
    float ls[2][2] = {{0.f, 0.f}, {0.f, 0.f}};

    const int qbase = 16384 + w * 2048;

    for (int kb = kb0; kb < kb0 + KV_SPLIT_TILES; kb++) {
        cp_wait<0>();
        __syncthreads();

        if (kb + 1 < kb0 + KV_SPLIT_TILES) {
            const int nb = (kb + 1) & 1;
            const __half* gk = g_Kh + ((size_t)(b * 32 + kb + 1) * 8 + h) * 4096;
            const __half* gv = g_Vh + ((size_t)(b * 32 + kb + 1) * 8 + h) * 4096;
            #pragma unroll
            for (int i = 0; i < 4; i++) {
                int off = i * 1024 + tid * 8;
                cp_async16(sb + (nb * 4096 + off) * 2, gk + off);
                cp_async16(sb + (8192 + nb * 4096 + off) * 2, gv + off);
            }
            cp_commit();
        }

        const int kbo = (kb & 1) * 4096;

        float s[2][8][4];
        #pragma unroll
        for (int mt = 0; mt < 2; mt++)
            #pragma unroll
            for (int nt = 0; nt < 8; nt++)
                #pragma unroll
                for (int q = 0; q < 4; q++) s[mt][nt][q] = 0.f;

        #pragma unroll
        for (int kk = 0; kk < 4; kk++) {
            uint32_t af[2][4];
            #pragma unroll
            for (int mt = 0; mt < 2; mt++) {
                float4 a4 = *(const float4*)&smha[qbase + mt * 1024
                                                  + kk * 256 + lane * 8];
                af[mt][0] = __float_as_uint(a4.x); af[mt][1] = __float_as_uint(a4.y);
                af[mt][2] = __float_as_uint(a4.z); af[mt][3] = __float_as_uint(a4.w);
            }
            #pragma unroll
            for (int nt = 0; nt < 8; nt++) {
                uint2 k2 = *(const uint2*)&smha[kbo + (kk * 8 + nt) * 128 + lane * 4];
                mma_f16(s[0][nt], af[0], k2.x, k2.y);
                mma_f16(s[1][nt], af[1], k2.x, k2.y);
            }
        }

        #pragma unroll
        for (int mt = 0; mt < 2; mt++) {
            const float* bLo = bias
                + ((size_t)b * NQS + q0 + 32 * w + 16 * mt + gid) * NKS + kb * 64;
            const float* bHi = bLo + 8 * (size_t)NKS;

            float rmLo = -1e30f, rmHi = -1e30f;
            #pragma unroll
            for (int nt = 0; nt < 8; nt++) {
                float2 bl = *(const float2*)(bLo + nt * 8 + 2 * tig);
                float2 bh = *(const float2*)(bHi + nt * 8 + 2 * tig);
                s[mt][nt][0] += bl.x;  s[mt][nt][1] += bl.y;
                s[mt][nt][2] += bh.x;  s[mt][nt][3] += bh.y;
                rmLo = fmaxf(rmLo, fmaxf(s[mt][nt][0], s[mt][nt][1]));
                rmHi = fmaxf(rmHi, fmaxf(s[mt][nt][2], s[mt][nt][3]));
            }
            rmLo = fmaxf(rmLo, __shfl_xor_sync(0xffffffffu, rmLo, 1));
            rmLo = fmaxf(rmLo, __shfl_xor_sync(0xffffffffu, rmLo, 2));
            rmHi = fmaxf(rmHi, __shfl_xor_sync(0xffffffffu, rmHi, 1));
            rmHi = fmaxf(rmHi, __shfl_xor_sync(0xffffffffu, rmHi, 2));

            const float mnLo = fmaxf(mx[mt][0], rmLo);
            const float mnHi = fmaxf(mx[mt][1], rmHi);
            const float corrLo = __expf(mx[mt][0] - mnLo);
            const float corrHi = __expf(mx[mt][1] - mnHi);
            mx[mt][0] = mnLo; mx[mt][1] = mnHi;

            float rsLo = 0.f, rsHi = 0.f;
            #pragma unroll
            for (int nt = 0; nt < 8; nt++) {
                float p0 = __expf(s[mt][nt][0] - mnLo);
                float p1 = __expf(s[mt][nt][1] - mnLo);
                float p2 = __expf(s[mt][nt][2] - mnHi);
                float p3 = __expf(s[mt][nt][3] - mnHi);
                rsLo += p0 + p1;
                rsHi += p2 + p3;
                s[mt][nt][0] = p0; s[mt][nt][1] = p1;
                s[mt][nt][2] = p2; s[mt][nt][3] = p3;
                o[mt][nt][0] *= corrLo; o[mt][nt][1] *= corrLo;
                o[mt][nt][2] *= corrHi; o[mt][nt][3] *= corrHi;
            }
            rsLo += __shfl_xor_sync(0xffffffffu, rsLo, 1);
            rsLo += __shfl_xor_sync(0xffffffffu, rsLo, 2);
            rsHi += __shfl_xor_sync(0xffffffffu, rsHi, 1);
            rsHi += __shfl_xor_sync(0xffffffffu, rsHi, 2);
            ls[mt][0] = ls[mt][0] * corrLo + rsLo;
            ls[mt][1] = ls[mt][1] * corrHi + rsHi;
        }

        #pragma unroll
        for (int kk = 0; kk < 4; kk++) {
            uint32_t af[2][4];
            #pragma unroll
            for (int mt = 0; mt < 2; mt++) {
                af[mt][0] = h2u(s[mt][2 * kk][0],     s[mt][2 * kk][1]);
                af[mt][1] = h2u(s[mt][2 * kk][2],     s[mt][2 * kk][3]);
                af[mt][2] = h2u(s[mt][2 * kk + 1][0], s[mt][2 * kk + 1][1]);
                af[mt][3] = h2u(s[mt][2 * kk + 1][2], s[mt][2 * kk + 1][3]);
            }
            #pragma unroll
            for (int nt = 0; nt < 8; nt++) {
                uint2 v2 = *(const uint2*)&smha[8192 + kbo
                                                + (kk * 8 + nt) * 128 + lane * 4];
                mma_f16(o[0][nt], af[0], v2.x, v2.y);
                mma_f16(o[1][nt], af[1], v2.x, v2.y);
            }
        }
    }

    float* Opart = split ? g_AO2 : g_AO;
    #pragma unroll
    for (int mt = 0; mt < 2; mt++) {
        const int rowLo = q0 + 32 * w + 16 * mt + gid;
        float* OgLo = Opart + ((size_t)b * NQS + rowLo) * DM + h * DH;
        float* OgHi = OgLo + 8 * (size_t)DM;
        #pragma unroll
        for (int nt = 0; nt < 8; nt++) {
            int col = nt * 8 + 2 * tig;
            *(float2*)(OgLo + col) = make_float2(o[mt][nt][0], o[mt][nt][1]);
            *(float2*)(OgHi + col) = make_float2(o[mt][nt][2], o[mt][nt][3]);
        }
        if (tig == 0) {
            int mi = (b * 8 + h) * 1024 + rowLo;
            g_M[split][mi]     = mx[mt][0];
            g_L[split][mi]     = ls[mt][0];
            g_M[split][mi + 8] = mx[mt][1];
            g_L[split][mi + 8] = ls[mt][1];
        }
    }
}

// ===========================================================================
// Merge the two KV splits; emit fp16 directly (A operand of output GEMM).
// ===========================================================================
__global__ __launch_bounds__(256) void merge_kernel()
{
    const size_t i = (size_t)blockIdx.x * 256 + threadIdx.x;   // per float2
    const size_t e = i * 2;
    const size_t row = e / DM;
    const int d  = (int)(e % DM);
    const int b  = (int)(row >> 10);
    const int q  = (int)(row & 1023);
    const int h  = d >> 6;
    const int mi = (b * 8 + h) * 1024 + q;

    const float m0 = g_M[0][mi], m1 = g_M[1][mi];
    const float l0 = g_L[0][mi], l1 = g_L[1][mi];
    const float ms = fmaxf(m0, m1);
    const float a0 = __expf(m0 - ms), a1 = __expf(m1 - ms);
    const float inv = 1.f / (l0 * a0 + l1 * a1);

    const float2 o0 = *(const float2*)&g_AO [e];
    const float2 o1 = *(const float2*)&g_AO2[e];
    *(uint32_t*)&g_AOh[e] = h2u((o0.x * a0 + o1.x * a1) * inv,
                                (o0.y * a0 + o1.y * a1) * inv);
}

// ---------------------------------------------------------------------------
// Launch
// ---------------------------------------------------------------------------
extern "C" void kernel_launch(void* const* d_in, const int* in_sizes, int n_in,
                              void* d_out, int out_size)
{
    const float* x    = (const float*)d_in[0];
    const float* ctx  = (const float*)d_in[1];
    const float* bias = (const float*)d_in[2];
    const float* Wq   = (const float*)d_in[3];
    const float* Wk   = (const float*)d_in[4];
    const float* Wv   = (const float*)d_in[5];
    const float* Wo   = (const float*)d_in[6];
    const float* bo   = (const float*)d_in[7];
    float* out = (float*)d_out;

    cudaFuncSetAttribute(gemm_h_kernel<0>,
                         cudaFuncAttributeMaxDynamicSharedMemorySize, GEMM_SMEM);
    cudaFuncSetAttribute(gemm_h_kernel<1>,
                         cudaFuncAttributeMaxDynamicSharedMemorySize, GEMM_SMEM);
    cudaFuncSetAttribute(gemm_h_kernel<2>,
                         cudaFuncAttributeMaxDynamicSharedMemorySize, GEMM_SMEM);
    cudaFuncSetAttribute(gemm_h_kernel<3>,
                         cudaFuncAttributeMaxDynamicSharedMemorySize, GEMM_SMEM);
    cudaFuncSetAttribute(attn_kernel,
                         cudaFuncAttributeMaxDynamicSharedMemorySize, ATTN_SMEM);

    void *gXh, *gCtxh, *gWqh, *gWkh, *gWvh, *gWoh, *gQh, *gKh, *gVh, *gAOh;
    cudaGetSymbolAddress(&gXh,   g_Xh);
    cudaGetSymbolAddress(&gCtxh, g_Ctxh);
    cudaGetSymbolAddress(&gWqh,  g_Wqh);
    cudaGetSymbolAddress(&gWkh,  g_Wkh);
    cudaGetSymbolAddress(&gWvh,  g_Wvh);
    cudaGetSymbolAddress(&gWoh,  g_Woh);
    cudaGetSymbolAddress(&gQh,   g_Qh);
    cudaGetSymbolAddress(&gKh,   g_Kh);
    cudaGetSymbolAddress(&gVh,   g_Vh);
    cudaGetSymbolAddress(&gAOh,  g_AOh);

    // fp32 -> fp16 conversions
    const int nx  = BATCH * NQS * DM / 4;   // 524288
    const int nc  = BATCH * NKS * DM / 4;   // 1048576
    const int nw  = DM * DM / 4;            // 65536
    f32to16_kernel<<<nx / 256, 256>>>(x,   (__half*)gXh,   nx);
    f32to16_kernel<<<nc / 256, 256>>>(ctx, (__half*)gCtxh, nc);
    f32to16_kernel<<<nw / 256, 256>>>(Wq,  (__half*)gWqh,  nw);
    f32to16_kernel<<<nw / 256, 256>>>(Wk,  (__half*)gWkh,  nw);
    f32to16_kernel<<<nw / 256, 256>>>(Wv,  (__half*)gWvh,  nw);
    f32to16_kernel<<<nw / 256, 256>>>(Wo,  (__half*)gWoh,  nw);

    dim3 gblk(256);
    gemm_h_kernel<1><<<dim3(4, (BATCH * NQS) / 128), gblk, GEMM_SMEM>>>(
        (const __half*)gXh,   (const __half*)gWqh, nullptr, (float*)gQh, 0);
    gemm_h_kernel<2><<<dim3(4, (BATCH * NKS) / 128), gblk, GEMM_SMEM>>>(
        (const __half*)gCtxh, (const __half*)gWkh, nullptr, (float*)gKh, 0);
    gemm_h_kernel<3><<<dim3(4, (BATCH * NKS) / 128), gblk, GEMM_SMEM>>>(
        (const __half*)gCtxh, (const __half*)gWvh, nullptr, (float*)gVh, 0);
    attn_kernel<<<dim3((NQS / 128) * 2, NHEADS, BATCH), dim3(128), ATTN_SMEM>>>(bias);
    merge_kernel<<<(BATCH * NQS * DM / 2) / 256, 256>>>();
    gemm_h_kernel<0><<<dim3(4, (BATCH * NQS) / 128), gblk, GEMM_SMEM>>>(
        (const __half*)gAOh, (const __half*)gWoh, bo, out, 1);
}

// round 9
// speedup vs baseline: 4.9635x; 1.1116x over previous
#include <cuda_runtime.h>
#include <cuda_fp16.h>
#include <cstdint>
#include <math.h>

#define NHEADS 8
#define DH     64
#define BATCH  4
#define NQS    1024
#define NKS    2048
#define DM     512
#define NSPLIT 4

// fp16 copies of inputs (converted once per run).
__device__ __half g_Xh  [(size_t)BATCH * NQS * DM];
__device__ __half g_Ctxh[(size_t)BATCH * NKS * DM];
__device__ __half g_Wqh[DM * DM];
__device__ __half g_Wkh[DM * DM];
__device__ __half g_Wvh[DM * DM];
__device__ __half g_Woh[DM * DM];
// Packed fp16 fragment buffers (mma-fragment order).
__device__ __half g_Qh[(size_t)BATCH * NQS * DM];
__device__ __half g_Kh[(size_t)BATCH * NKS * DM];
__device__ __half g_Vh[(size_t)BATCH * NKS * DM];
// Split-KV partial outputs (unnormalized, fp32) + (m, l) per row per split.
__device__ float  g_Part[NSPLIT][(size_t)BATCH * NQS * DM];
__device__ float  g_M[NSPLIT][BATCH * NHEADS * NQS];
__device__ float  g_L[NSPLIT][BATCH * NHEADS * NQS];
// Merged attention output in fp16 (A operand of the output GEMM).
__device__ __half g_AOh[(size_t)BATCH * NQS * DM];

// ===========================================================================
// Helpers
// ===========================================================================
__device__ __forceinline__ uint32_t smem_u32(const void* p) {
    uint32_t a;
    asm("{ .reg .u64 t; cvta.to.shared.u64 t, %1; cvt.u32.u64 %0, t; }"
        : "=r"(a) : "l"(p));
    return a;
}
__device__ __forceinline__ void mma_f16(float c[4], const uint32_t a[4],
                                        uint32_t b0, uint32_t b1) {
    asm volatile(
        "mma.sync.aligned.m16n8k16.row.col.f32.f16.f16.f32 "
        "{%0,%1,%2,%3}, {%4,%5,%6,%7}, {%8,%9}, {%0,%1,%2,%3};"
        : "+f"(c[0]), "+f"(c[1]), "+f"(c[2]), "+f"(c[3])
        : "r"(a[0]), "r"(a[1]), "r"(a[2]), "r"(a[3]), "r"(b0), "r"(b1));
}
__device__ __forceinline__ void ldsm_x4(uint32_t r[4], uint32_t addr) {
    asm volatile("ldmatrix.sync.aligned.m8n8.x4.shared.b16 {%0,%1,%2,%3}, [%4];"
                 : "=r"(r[0]), "=r"(r[1]), "=r"(r[2]), "=r"(r[3]) : "r"(addr));
}
__device__ __forceinline__ void ldsm_x2(uint32_t r[2], uint32_t addr) {
    asm volatile("ldmatrix.sync.aligned.m8n8.x2.shared.b16 {%0,%1}, [%2];"
                 : "=r"(r[0]), "=r"(r[1]) : "r"(addr));
}
__device__ __forceinline__ uint32_t h2u(float lo, float hi) {
    __half2 v = __floats2half2_rn(lo, hi);
    return *(uint32_t*)&v;
}
__device__ __forceinline__ void cp_async16(uint32_t s, const void* g) {
    asm volatile("cp.async.ca.shared.global [%0], [%1], 16;"
                 :: "r"(s), "l"(g) : "memory");
}
__device__ __forceinline__ void cp_commit() {
    asm volatile("cp.async.commit_group;" ::: "memory");
}
template<int N> __device__ __forceinline__ void cp_wait() {
    asm volatile("cp.async.wait_group %0;" :: "n"(N) : "memory");
}

// ===========================================================================
// fp32 -> fp16 conversions
// ===========================================================================
__global__ __launch_bounds__(256) void f32to16_kernel(
    const float* __restrict__ src, __half* __restrict__ dst, int n4)
{
    int i = blockIdx.x * 256 + threadIdx.x;
    if (i < n4) {
        float4 v = ((const float4*)src)[i];
        *(uint2*)&dst[(size_t)i * 4] = make_uint2(h2u(v.x, v.y), h2u(v.z, v.w));
    }
}
// Fused conversion of the 4 weight matrices (each 512x512).
__global__ __launch_bounds__(256) void f32to16_w4_kernel(
    const float* __restrict__ s0, const float* __restrict__ s1,
    const float* __restrict__ s2, const float* __restrict__ s3)
{
    const int i = blockIdx.x * 256 + threadIdx.x;   // 0 .. 4*65536-1
    const int t = i >> 16;                          // tensor index
    const int j = i & 65535;                        // float4 index
    const float* src = (t == 0) ? s0 : (t == 1) ? s1 : (t == 2) ? s2 : s3;
    __half* dst = (t == 0) ? g_Wqh : (t == 1) ? g_Wkh : (t == 2) ? g_Wvh : g_Woh;
    float4 v = ((const float4*)src)[j];
    *(uint2*)&dst[(size_t)j * 4] = make_uint2(h2u(v.x, v.y), h2u(v.z, v.w));
}

// ===========================================================================
// GEMM: C[M,512] = A[M,512] @ W[512,512]^T.  fp16 mma (m16n8k16), f32 accum.
// CTA 128x128, BK=32 halves, cp.async double buffer, 8 warps (2m x 4n),
// warp 64x32, ldmatrix fragment loads, smem pitch 40 halves.
// MODE 0: fp32 store (+bias). MODE 1: Q A-frag pack (x0.125).
// MODE 2: K B-frag pack. MODE 3: V B-frag pack.
// ===========================================================================
#define GBKH    32
#define GPITCHH 40
#define GTILEH  (128 * GPITCHH)
#define GEMM_SMEM (4 * GTILEH * 2)

template<int MODE>
__global__ __launch_bounds__(256, 2) void gemm_h_kernel(
    const __half* __restrict__ A, const __half* __restrict__ W,
    const float* __restrict__ bias, float* __restrict__ C, int addBias)
{
    extern __shared__ __half smh[];
    const uint32_t sb = smem_u32(smh);

    const int tid  = threadIdx.x;
    const int w    = tid >> 5;
    const int lane = tid & 31;
    const int gid  = lane >> 2;
    const int tig  = lane & 3;
    const int wm   = (w >> 2) * 64;
    const int wn   = (w & 3) * 32;
    const int m0   = blockIdx.y * 128;
    const int n0   = blockIdx.x * 128;

    float acc[4][4][4];
    #pragma unroll
    for (int mt = 0; mt < 4; mt++)
        #pragma unroll
        for (int nt = 0; nt < 4; nt++)
            #pragma unroll
            for (int q = 0; q < 4; q++) acc[mt][nt][q] = 0.f;

    auto stage_load = [&](int buf, int ks) {
        const int k0 = ks * GBKH;
        const uint32_t sA = sb + (uint32_t)(buf * GTILEH) * 2u;
        const uint32_t sW = sb + (uint32_t)(2 * GTILEH + buf * GTILEH) * 2u;
        #pragma unroll
        for (int i = 0; i < 2; i++) {
            int idx = tid + 256 * i;
            int r   = idx >> 2;
            int c   = (idx & 3) * 8;
            cp_async16(sA + (uint32_t)(r * GPITCHH + c) * 2u,
                       A + (size_t)(m0 + r) * DM + k0 + c);
            cp_async16(sW + (uint32_t)(r * GPITCHH + c) * 2u,
                       W + (size_t)(n0 + r) * DM + k0 + c);
        }
        cp_commit();
    };

    const int NST = DM / GBKH;
    stage_load(0, 0);
    stage_load(1, 1);

    const int aRow = ((lane >> 3) & 1) * 8 + (lane & 7);
    const int aK   = ((lane >> 4) & 1) * 8;
    const int bRow = lane & 7;
    const int bK   = ((lane >> 3) & 1) * 8;

    for (int ks = 0; ks < NST; ++ks) {
        cp_wait<1>();
        __syncthreads();

        const uint32_t aBase = sb + (uint32_t)((ks & 1) * GTILEH) * 2u;
        const uint32_t bBase = sb + (uint32_t)(2 * GTILEH + (ks & 1) * GTILEH) * 2u;

        #pragma unroll
        for (int kst = 0; kst < 2; kst++) {
            uint32_t af[4][4];
            #pragma unroll
            for (int mt = 0; mt < 4; mt++)
                ldsm_x4(af[mt], aBase
                        + (uint32_t)((wm + mt * 16 + aRow) * GPITCHH
                                     + kst * 16 + aK) * 2u);
            uint32_t bf[4][2];
            #pragma unroll
            for (int nt = 0; nt < 4; nt++)
                ldsm_x2(bf[nt], bBase
                        + (uint32_t)((wn + nt * 8 + bRow) * GPITCHH
                                     + kst * 16 + bK) * 2u);
            #pragma unroll
            for (int mt = 0; mt < 4; mt++)
                #pragma unroll
                for (int nt = 0; nt < 4; nt++)
                    mma_f16(acc[mt][nt], af[mt], bf[nt][0], bf[nt][1]);
        }
        __syncthreads();
        if (ks + 2 < NST) stage_load(ks & 1, ks + 2);
    }

    // ---------------- epilogue ----------------
    if (MODE == 0) {
        #pragma unroll
        for (int mt = 0; mt < 4; mt++) {
            const int r0 = m0 + wm + mt * 16 + gid;
            #pragma unroll
            for (int nt = 0; nt < 4; nt++) {
                const int col = n0 + wn + nt * 8 + 2 * tig;
                float b0 = 0.f, b1 = 0.f;
                if (addBias) { b0 = bias[col]; b1 = bias[col + 1]; }
                *(float2*)(C + (size_t)r0 * DM + col) =
                    make_float2(acc[mt][nt][0] + b0, acc[mt][nt][1] + b1);
                *(float2*)(C + (size_t)(r0 + 8) * DM + col) =
                    make_float2(acc[mt][nt][2] + b0, acc[mt][nt][3] + b1);
            }
        }
    } else {
        __half* Ch = reinterpret_cast<__half*>(C);
        #pragma unroll
        for (int mt = 0; mt < 4; mt++) {
            #pragma unroll
            for (int nt = 0; nt < 4; nt++) {
                #pragma unroll
                for (int q = 0; q < 4; q++) {
                    const int m   = m0 + wm + mt * 16 + gid + 8 * (q >> 1);
                    const int col = n0 + wn + nt * 8 + 2 * tig + (q & 1);
                    const int h = col >> 6, d = col & 63;
                    float val = acc[mt][nt][q];
                    size_t idx;
                    if (MODE == 1) {
                        int b  = m >> 10, qq = m & 1023;
                        int t  = qq >> 4, g = qq & 7, rh = (qq >> 3) & 1;
                        int kk = d >> 4, hi = (d >> 3) & 1;
                        int tq = (d & 7) >> 1, ev = d & 1;
                        idx = ((((size_t)((b * 8 + h) * 64 + t) * 4 + kk) * 256)
                              + (g * 4 + tq) * 8 + (rh + 2 * hi) * 2 + ev);
                        val *= 0.125f;
                    } else if (MODE == 2) {
                        int b = m >> 11, n = m & 2047;
                        int kt = n >> 6, ri = n & 63;
                        int nt2 = ri >> 3, g = ri & 7;
                        int kk = d >> 4, hi = (d >> 3) & 1;
                        int t = (d & 7) >> 1, ev = d & 1;
                        idx = (size_t)((b * 32 + kt) * 8 + h) * 4096
                              + (kk * 8 + nt2) * 128 + (g * 4 + t) * 4
                              + hi * 2 + ev;
                    } else {
                        int b = m >> 11, n = m & 2047;
                        int kt = n >> 6, kr = n & 63;
                        int kk = kr >> 4, hi = (kr >> 3) & 1;
                        int t = (kr & 7) >> 1, ev = kr & 1;
                        int nt2 = d >> 3, g = d & 7;
                        idx = (size_t)((b * 32 + kt) * 8 + h) * 4096
                              + (kk * 8 + nt2) * 128 + (g * 4 + t) * 4
                              + hi * 2 + ev;
                    }
                    Ch[idx] = __float2half_rn(val);
                }
            }
        }
    }
}

// ===========================================================================
// Flash attention, fp16 mma, f32 accumulate, P in registers, SPLIT-KV x4.
// Grid (32, 8, 4): blockIdx.x = qtile*4 + split; each CTA does 8 KV tiles.
// ===========================================================================
#define ATTN_SMEM 49152
#define KV_SPLIT_TILES (32 / NSPLIT)

__global__ __launch_bounds__(128, 3) void attn_kernel(const float* __restrict__ bias)
{
    extern __shared__ __half smha[];
    const uint32_t sb = smem_u32(smha);

    const int tid   = threadIdx.x;
    const int w     = tid >> 5;
    const int lane  = tid & 31;
    const int gid   = lane >> 2;
    const int tig   = lane & 3;
    const int split = blockIdx.x & (NSPLIT - 1);
    const int qt    = blockIdx.x / NSPLIT;
    const int q0    = qt * 128;
    const int h     = blockIdx.y;
    const int b     = blockIdx.z;
    const int kb0   = split * KV_SPLIT_TILES;

    {
        const __half* gq = g_Qh + (size_t)((b * 8 + h) * 64 + qt * 8) * 1024;
        #pragma unroll
        for (int i = 0; i < 8; i++) {
            int off = i * 1024 + tid * 8;
            cp_async16(sb + (16384 + off) * 2, gq + off);
        }
    }
    {
        const __half* gk = g_Kh + ((size_t)(b * 32 + kb0) * 8 + h) * 4096;
        const __half* gv = g_Vh + ((size_t)(b * 32 + kb0) * 8 + h) * 4096;
        #pragma unroll
        for (int i = 0; i < 4; i++) {
            int off = i * 1024 + tid * 8;
            cp_async16(sb + ((kb0 & 1) * 4096 + off) * 2, gk + off);
            cp_async16(sb + (8192 + (kb0 & 1) * 4096 + off) * 2, gv + off);
        }
    }
    cp_commit();

    float o[2][8][4];
    #pragma unroll
    for (int mt = 0; mt < 2; mt++)
        #pragma unroll
        for (int nt = 0; nt < 8; nt++)
            #pragma unroll
            for (int q = 0; q < 4; q++) o[mt][nt][q] = 0.f;
    float mx[2][2] = {{-1e30f, -1e30f}, {-1e30f, -1e30f}};
    float ls[2][2] = {{0.f, 0.f}, {0.f, 0.f}};

    const int qbase = 16384 + w * 2048;

    for (int kb = kb0; kb < kb0 + KV_SPLIT_TILES; kb++) {
        cp_wait<0>();
        __syncthreads();

        if (kb + 1 < kb0 + KV_SPLIT_TILES) {
            const int nb = (kb + 1) & 1;
            const __half* gk = g_Kh + ((size_t)(b * 32 + kb + 1) * 8 + h) * 4096;
            const __half* gv = g_Vh + ((size_t)(b * 32 + kb + 1) * 8 + h) * 4096;
            #pragma unroll
            for (int i = 0; i < 4; i++) {
                int off = i * 1024 + tid * 8;
                cp_async16(sb + (nb * 4096 + off) * 2, gk + off);
                cp_async16(sb + (8192 + nb * 4096 + off) * 2, gv + off);
            }
            cp_commit();
        }

        const int kbo = (kb & 1) * 4096;

        float s[2][8][4];
        #pragma unroll
        for (int mt = 0; mt < 2; mt++)
            #pragma unroll
            for (int nt = 0; nt < 8; nt++)
                #pragma unroll
                for (int q = 0; q < 4; q++) s[mt][nt][q] = 0.f;

        #pragma unroll
        for (int kk = 0; kk < 4; kk++) {
            uint32_t af[2][4];
            #pragma unroll
            for (int mt = 0; mt < 2; mt++) {
                float4 a4 = *(const float4*)&smha[qbase + mt * 1024
                                                  + kk * 256 + lane * 8];
                af[mt][0] = __float_as_uint(a4.x); af[mt][1] = __float_as_uint(a4.y);
                af[mt][2] = __float_as_uint(a4.z); af[mt][3] = __float_as_uint(a4.w);
            }
            #pragma unroll
            for (int nt = 0; nt < 8; nt++) {
                uint2 k2 = *(const uint2*)&smha[kbo + (kk * 8 + nt) * 128 + lane * 4];
                mma_f16(s[0][nt], af[0], k2.x, k2.y);
                mma_f16(s[1][nt], af[1], k2.x, k2.y);
            }
        }

        #pragma unroll
        for (int mt = 0; mt < 2; mt++) {
            const float* bLo = bias
                + ((size_t)b * NQS + q0 + 32 * w + 16 * mt + gid) * NKS + kb * 64;
            const float* bHi = bLo + 8 * (size_t)NKS;

            float rmLo = -1e30f, rmHi = -1e30f;
            #pragma unroll
            for (int nt = 0; nt < 8; nt++) {
                float2 bl = *(const float2*)(bLo + nt * 8 + 2 * tig);
                float2 bh = *(const float2*)(bHi + nt * 8 + 2 * tig);
                s[mt][nt][0] += bl.x;  s[mt][nt][1] += bl.y;
                s[mt][nt][2] += bh.x;  s[mt][nt][3] += bh.y;
                rmLo = fmaxf(rmLo, fmaxf(s[mt][nt][0], s[mt][nt][1]));
                rmHi = fmaxf(rmHi, fmaxf(s[mt][nt][2], s[mt][nt][3]));
            }
            rmLo = fmaxf(rmLo, __shfl_xor_sync(0xffffffffu, rmLo, 1));
            rmLo = fmaxf(rmLo, __shfl_xor_sync(0xffffffffu, rmLo, 2));
            rmHi = fmaxf(rmHi, __shfl_xor_sync(0xffffffffu, rmHi, 1));
            rmHi = fmaxf(rmHi, __shfl_xor_sync(0xffffffffu, rmHi, 2));

            const float mnLo = fmaxf(mx[mt][0], rmLo);
            const float mnHi = fmaxf(mx[mt][1], rmHi);
            const float corrLo = __expf(mx[mt][0] - mnLo);
            const float corrHi = __expf(mx[mt][1] - mnHi);
            mx[mt][0] = mnLo; mx[mt][1] = mnHi;

            float rsLo = 0.f, rsHi = 0.f;
            #pragma unroll
            for (int nt = 0; nt < 8; nt++) {
                float p0 = __expf(s[mt][nt][0] - mnLo);
                float p1 = __expf(s[mt][nt][1] - mnLo);
                float p2 = __expf(s[mt][nt][2] - mnHi);
                float p3 = __expf(s[mt][nt][3] - mnHi);
                rsLo += p0 + p1;
                rsHi += p2 + p3;
                s[mt][nt][0] = p0; s[mt][nt][1] = p1;
                s[mt][nt][2] = p2; s[mt][nt][3] = p3;
                o[mt][nt][0] *= corrLo; o[mt][nt][1] *= corrLo;
                o[mt][nt][2] *= corrHi; o[mt][nt][3] *= corrHi;
            }
            rsLo += __shfl_xor_sync(0xffffffffu, rsLo, 1);
            rsLo += __shfl_xor_sync(0xffffffffu, rsLo, 2);
            rsHi += __shfl_xor_sync(0xffffffffu, rsHi, 1);
            rsHi += __shfl_xor_sync(0xffffffffu, rsHi, 2);
            ls[mt][0] = ls[mt][0] * corrLo + rsLo;
            ls[mt][1] = ls[mt][1] * corrHi + rsHi;
        }

        #pragma unroll
        for (int kk = 0; kk < 4; kk++) {
            uint32_t af[2][4];
            #pragma unroll
            for (int mt = 0; mt < 2; mt++) {
                af[mt][0] = h2u(s[mt][2 * kk][0],     s[mt][2 * kk][1]);
                af[mt][1] = h2u(s[mt][2 * kk][2],     s[mt][2 * kk][3]);
                af[mt][2] = h2u(s[mt][2 * kk + 1][0], s[mt][2 * kk + 1][1]);
                af[mt][3] = h2u(s[mt][2 * kk + 1][2], s[mt][2 * kk + 1][3]);
            }
            #pragma unroll
            for (int nt = 0; nt < 8; nt++) {
                uint2 v2 = *(const uint2*)&smha[8192 + kbo
                                                + (kk * 8 + nt) * 128 + lane * 4];
                mma_f16(o[0][nt], af[0], v2.x, v2.y);
                mma_f16(o[1][nt], af[1], v2.x, v2.y);
            }
        }
    }

    float* Opart = g_Part[split];
    #pragma unroll
    for (int mt = 0; mt < 2; mt++) {
        const int rowLo = q0 + 32 * w + 16 * mt + gid;
        float* OgLo = Opart + ((size_t)b * NQS + rowLo) * DM + h * DH;
        float* OgHi = OgLo + 8 * (size_t)DM;
        #pragma unroll
        for (int nt = 0; nt < 8; nt++) {
            int col = nt * 8 + 2 * tig;
            *(float2*)(OgLo + col) = make_float2(o[mt][nt][0], o[mt][nt][1]);
            *(float2*)(OgHi + col) = make_float2(o[mt][nt][2], o[mt][nt][3]);
        }
        if (tig == 0) {
            int mi = (b * 8 + h) * 1024 + rowLo;
            g_M[split][mi]     = mx[mt][0];
            g_L[split][mi]     = ls[mt][0];
            g_M[split][mi + 8] = mx[mt][1];
            g_L[split][mi + 8] = ls[mt][1];
        }
    }
}

// ===========================================================================
// Merge the NSPLIT KV splits; emit fp16 (A operand of output GEMM).
// ===========================================================================
__global__ __launch_bounds__(256) void merge_kernel()
{
    const size_t i = (size_t)blockIdx.x * 256 + threadIdx.x;   // per float2
    const size_t e = i * 2;
    const size_t row = e / DM;
    const int d  = (int)(e % DM);
    const int b  = (int)(row >> 10);
    const int q  = (int)(row & 1023);
    const int h  = d >> 6;
    const int mi = (b * 8 + h) * 1024 + q;

    float m[NSPLIT], l[NSPLIT];
    float ms = -1e30f;
    #pragma unroll
    for (int s = 0; s < NSPLIT; s++) {
        m[s] = g_M[s][mi];
        l[s] = g_L[s][mi];
        ms = fmaxf(ms, m[s]);
    }
    float den = 0.f;
    float a[NSPLIT];
    #pragma unroll
    for (int s = 0; s < NSPLIT; s++) {
        a[s] = __expf(m[s] - ms);
        den += l[s] * a[s];
    }
    const float inv = 1.f / den;

    float ox = 0.f, oy = 0.f;
    #pragma unroll
    for (int s = 0; s < NSPLIT; s++) {
        const float2 p = *(const float2*)&g_Part[s][e];
        ox += p.x * a[s];
        oy += p.y * a[s];
    }
    *(uint32_t*)&g_AOh[e] = h2u(ox * inv, oy * inv);
}

// ---------------------------------------------------------------------------
// Launch
// ---------------------------------------------------------------------------
extern "C" void kernel_launch(void* const* d_in, const int* in_sizes, int n_in,
                              void* d_out, int out_size)
{
    const float* x    = (const float*)d_in[0];
    const float* ctx  = (const float*)d_in[1];
    const float* bias = (const float*)d_in[2];
    const float* Wq   = (const float*)d_in[3];
    const float* Wk   = (const float*)d_in[4];
    const float* Wv   = (const float*)d_in[5];
    const float* Wo   = (const float*)d_in[6];
    const float* bo   = (const float*)d_in[7];
    float* out = (float*)d_out;

    cudaFuncSetAttribute(gemm_h_kernel<0>,
                         cudaFuncAttributeMaxDynamicSharedMemorySize, GEMM_SMEM);
    cudaFuncSetAttribute(gemm_h_kernel<1>,
                         cudaFuncAttributeMaxDynamicSharedMemorySize, GEMM_SMEM);
    cudaFuncSetAttribute(gemm_h_kernel<2>,
                         cudaFuncAttributeMaxDynamicSharedMemorySize, GEMM_SMEM);
    cudaFuncSetAttribute(gemm_h_kernel<3>,
                         cudaFuncAttributeMaxDynamicSharedMemorySize, GEMM_SMEM);
    cudaFuncSetAttribute(attn_kernel,
                         cudaFuncAttributeMaxDynamicSharedMemorySize, ATTN_SMEM);

    void *gXh, *gCtxh, *gWqh, *gWkh, *gWvh, *gWoh, *gQh, *gKh, *gVh, *gAOh;
    cudaGetSymbolAddress(&gXh,   g_Xh);
    cudaGetSymbolAddress(&gCtxh, g_Ctxh);
    cudaGetSymbolAddress(&gWqh,  g_Wqh);
    cudaGetSymbolAddress(&gWkh,  g_Wkh);
    cudaGetSymbolAddress(&gWvh,  g_Wvh);
    cudaGetSymbolAddress(&gWoh,  g_Woh);
    cudaGetSymbolAddress(&gQh,   g_Qh);
    cudaGetSymbolAddress(&gKh,   g_Kh);
    cudaGetSymbolAddress(&gVh,   g_Vh);
    cudaGetSymbolAddress(&gAOh,  g_AOh);

    const int nx = BATCH * NQS * DM / 4;
    const int nc = BATCH * NKS * DM / 4;
    f32to16_kernel<<<nx / 256, 256>>>(x,   (__half*)gXh,   nx);
    f32to16_kernel<<<nc / 256, 256>>>(ctx, (__half*)gCtxh, nc);
    f32to16_w4_kernel<<<4 * 65536 / 256, 256>>>(Wq, Wk, Wv, Wo);

    dim3 gblk(256);
    gemm_h_kernel<1><<<dim3(4, (BATCH * NQS) / 128), gblk, GEMM_SMEM>>>(
        (const __half*)gXh,   (const __half*)gWqh, nullptr, (float*)gQh, 0);
    gemm_h_kernel<2><<<dim3(4, (BATCH * NKS) / 128), gblk, GEMM_SMEM>>>(
        (const __half*)gCtxh, (const __half*)gWkh, nullptr, (float*)gKh, 0);
    gemm_h_kernel<3><<<dim3(4, (BATCH * NKS) / 128), gblk, GEMM_SMEM>>>(
        (const __half*)gCtxh, (const __half*)gWvh, nullptr, (float*)gVh, 0);
    attn_kernel<<<dim3((NQS / 128) * NSPLIT, NHEADS, BATCH),
                  dim3(128), ATTN_SMEM>>>(bias);
    merge_kernel<<<(BATCH * NQS * DM / 2) / 256, 256>>>();
    gemm_h_kernel<0><<<dim3(4, (BATCH * NQS) / 128), gblk, GEMM_SMEM>>>(
        (const __half*)gAOh, (const __half*)gWoh, bo, out, 1);
}

// round 11
// speedup vs baseline: 5.1325x; 1.0341x over previous
#include <cuda_runtime.h>
#include <cuda_fp16.h>
#include <cstdint>
#include <math.h>

#define NHEADS 8
#define DH     64
#define BATCH  4
#define NQS    1024
#define NKS    2048
#define DM     512
#define NSPLIT 4

// fp16 copies of inputs (converted once per run).
__device__ __half g_Xh  [(size_t)BATCH * NQS * DM];
__device__ __half g_Ctxh[(size_t)BATCH * NKS * DM];
__device__ __half g_Wqh[DM * DM];
__device__ __half g_Wkh[DM * DM];
__device__ __half g_Wvh[DM * DM];
__device__ __half g_Woh[DM * DM];
// Packed fp16 fragment buffers (mma-fragment order).
__device__ __half g_Qh[(size_t)BATCH * NQS * DM];
__device__ __half g_Kh[(size_t)BATCH * NKS * DM];
__device__ __half g_Vh[(size_t)BATCH * NKS * DM];
// Split-KV partial outputs (unnormalized, fp32) + (m, l) per row per split.
__device__ float  g_Part[NSPLIT][(size_t)BATCH * NQS * DM];
__device__ float  g_M[NSPLIT][BATCH * NHEADS * NQS];
__device__ float  g_L[NSPLIT][BATCH * NHEADS * NQS];
// Merged attention output in fp16 (A operand of the output GEMM).
__device__ __half g_AOh[(size_t)BATCH * NQS * DM];

// ===========================================================================
// Helpers
// ===========================================================================
__device__ __forceinline__ uint32_t smem_u32(const void* p) {
    uint32_t a;
    asm("{ .reg .u64 t; cvta.to.shared.u64 t, %1; cvt.u32.u64 %0, t; }"
        : "=r"(a) : "l"(p));
    return a;
}
__device__ __forceinline__ void mma_f16(float c[4], const uint32_t a[4],
                                        uint32_t b0, uint32_t b1) {
    asm volatile(
        "mma.sync.aligned.m16n8k16.row.col.f32.f16.f16.f32 "
        "{%0,%1,%2,%3}, {%4,%5,%6,%7}, {%8,%9}, {%0,%1,%2,%3};"
        : "+f"(c[0]), "+f"(c[1]), "+f"(c[2]), "+f"(c[3])
        : "r"(a[0]), "r"(a[1]), "r"(a[2]), "r"(a[3]), "r"(b0), "r"(b1));
}
__device__ __forceinline__ void ldsm_x4(uint32_t r[4], uint32_t addr) {
    asm volatile("ldmatrix.sync.aligned.m8n8.x4.shared.b16 {%0,%1,%2,%3}, [%4];"
                 : "=r"(r[0]), "=r"(r[1]), "=r"(r[2]), "=r"(r[3]) : "r"(addr));
}
__device__ __forceinline__ void ldsm_x2(uint32_t r[2], uint32_t addr) {
    asm volatile("ldmatrix.sync.aligned.m8n8.x2.shared.b16 {%0,%1}, [%2];"
                 : "=r"(r[0]), "=r"(r[1]) : "r"(addr));
}
__device__ __forceinline__ uint32_t h2u(float lo, float hi) {
    __half2 v = __floats2half2_rn(lo, hi);
    return *(uint32_t*)&v;
}
__device__ __forceinline__ void cp_async16(uint32_t s, const void* g) {
    asm volatile("cp.async.ca.shared.global [%0], [%1], 16;"
                 :: "r"(s), "l"(g) : "memory");
}
__device__ __forceinline__ void cp_commit() {
    asm volatile("cp.async.commit_group;" ::: "memory");
}
template<int N> __device__ __forceinline__ void cp_wait() {
    asm volatile("cp.async.wait_group %0;" :: "n"(N) : "memory");
}

// ===========================================================================
// Fused fp32 -> fp16 conversion of x, ctx and the 4 weights (one launch).
// ===========================================================================
#define NX4 (BATCH * NQS * DM / 4)          // 524288
#define NC4 (BATCH * NKS * DM / 4)          // 1048576
#define NW4 (DM * DM / 4)                   // 65536
#define CONV_BLOCKS ((NX4 + NC4 + 4 * NW4) / 256)

__global__ __launch_bounds__(256) void conv_all_kernel(
    const float* __restrict__ x,  const float* __restrict__ ctx,
    const float* __restrict__ w0, const float* __restrict__ w1,
    const float* __restrict__ w2, const float* __restrict__ w3)
{
    const int i = blockIdx.x * 256 + threadIdx.x;
    const float* src;
    __half* dst;
    int j;
    if (i < NX4)                 { src = x;   dst = g_Xh;   j = i; }
    else if (i < NX4 + NC4)      { src = ctx; dst = g_Ctxh; j = i - NX4; }
    else {
        const int k = i - NX4 - NC4;
        const int t = k >> 16;
        j = k & 65535;
        src = (t == 0) ? w0 : (t == 1) ? w1 : (t == 2) ? w2 : w3;
        dst = (t == 0) ? g_Wqh : (t == 1) ? g_Wkh : (t == 2) ? g_Wvh : g_Woh;
    }
    float4 v = ((const float4*)src)[j];
    *(uint2*)&dst[(size_t)j * 4] = make_uint2(h2u(v.x, v.y), h2u(v.z, v.w));
}

// ===========================================================================
// GEMM mainloop core: C[M,512] = A[M,512] @ W[512,512]^T, fp16 mma.
// CTA tile 128(M) x 64(N), BK=32 halves, 3-stage cp.async, 128 threads
// (4 warps, 2m x 2n, warp 64x32), ldmatrix frag loads, pitch 40 halves.
// PIPELINE INVARIANT: exactly one commit_group per iteration (empty commits
// in the tail) so cp_wait<2> always guarantees stage ks has landed.
// ===========================================================================
#define GBKH    32
#define GPITCHH 40
#define GA_H    (128 * GPITCHH)          // A stage: 5120 halves
#define GB_H    (64 * GPITCHH)           // B stage: 2560 halves
#define GSTG_H  (GA_H + GB_H)            // 7680 halves = 15360 B
#define GEMM_SMEM (3 * GSTG_H * 2)       // 46080 B

__device__ __forceinline__ void gemm_mainloop(
    const __half* __restrict__ A, const __half* __restrict__ W,
    int m0, int n0, uint32_t sb, float acc[4][4][4],
    int lane, int wm, int wn)
{
    const int tid = threadIdx.x;

    auto stage_load = [&](int buf, int ks) {
        const int k0 = ks * GBKH;
        const uint32_t sA = sb + (uint32_t)(buf * GSTG_H) * 2u;
        const uint32_t sB = sA + (uint32_t)GA_H * 2u;
        #pragma unroll
        for (int i = 0; i < 4; i++) {           // A: 512 chunks
            int idx = tid + 128 * i;
            int r = idx >> 2, c = (idx & 3) * 8;
            cp_async16(sA + (uint32_t)(r * GPITCHH + c) * 2u,
                       A + (size_t)(m0 + r) * DM + k0 + c);
        }
        #pragma unroll
        for (int i = 0; i < 2; i++) {           // B: 256 chunks
            int idx = tid + 128 * i;
            int r = idx >> 2, c = (idx & 3) * 8;
            cp_async16(sB + (uint32_t)(r * GPITCHH + c) * 2u,
                       W + (size_t)(n0 + r) * DM + k0 + c);
        }
        cp_commit();
    };

    const int NST = DM / GBKH;   // 16
    stage_load(0, 0);
    stage_load(1, 1);
    stage_load(2, 2);

    const int aRow = ((lane >> 3) & 1) * 8 + (lane & 7);
    const int aK   = ((lane >> 4) & 1) * 8;
    const int bRow = lane & 7;
    const int bK   = ((lane >> 3) & 1) * 8;

    int buf = 0;
    for (int ks = 0; ks < NST; ++ks) {
        cp_wait<2>();
        __syncthreads();

        const uint32_t aBase = sb + (uint32_t)(buf * GSTG_H) * 2u;
        const uint32_t bBase = aBase + (uint32_t)GA_H * 2u;

        #pragma unroll
        for (int kst = 0; kst < 2; kst++) {
            uint32_t af[4][4];
            #pragma unroll
            for (int mt = 0; mt < 4; mt++)
                ldsm_x4(af[mt], aBase
                        + (uint32_t)((wm + mt * 16 + aRow) * GPITCHH
                                     + kst * 16 + aK) * 2u);
            uint32_t bf[4][2];
            #pragma unroll
            for (int nt = 0; nt < 4; nt++)
                ldsm_x2(bf[nt], bBase
                        + (uint32_t)((wn + nt * 8 + bRow) * GPITCHH
                                     + kst * 16 + bK) * 2u);
            #pragma unroll
            for (int mt = 0; mt < 4; mt++)
                #pragma unroll
                for (int nt = 0; nt < 4; nt++)
                    mma_f16(acc[mt][nt], af[mt], bf[nt][0], bf[nt][1]);
        }
        __syncthreads();
        // Keep the one-commit-per-iteration invariant (empty commit in tail)
        if (ks + 3 < NST) stage_load(buf, ks + 3);
        else              cp_commit();
        buf = (buf == 2) ? 0 : buf + 1;
    }
}

// ---------------------------------------------------------------------------
// Fused Q/K/V projection GEMM. Linear grid: [0,256)=Q, [256,768)=K,
// [768,1280)=V. Epilogue packs mma-fragment layouts (Q pre-scaled 0.125).
// ---------------------------------------------------------------------------
__global__ __launch_bounds__(128, 4) void gemm_qkv_kernel()
{
    extern __shared__ __half smh[];
    const uint32_t sb = smem_u32(smh);

    const int tid  = threadIdx.x;
    const int w    = tid >> 5;
    const int lane = tid & 31;
    const int gid  = lane >> 2;
    const int tig  = lane & 3;
    const int wm   = (w >> 1) * 64;
    const int wn   = (w & 1) * 32;

    int id = blockIdx.x, mode;
    const __half *A, *W;
    __half *C;
    if (id < 256)      { mode = 1; A = g_Xh;   W = g_Wqh; C = g_Qh; }
    else if (id < 768) { mode = 2; id -= 256; A = g_Ctxh; W = g_Wkh; C = g_Kh; }
    else               { mode = 3; id -= 768; A = g_Ctxh; W = g_Wvh; C = g_Vh; }
    const int m0 = (id >> 3) * 128;
    const int n0 = (id & 7) * 64;

    float acc[4][4][4];
    #pragma unroll
    for (int mt = 0; mt < 4; mt++)
        #pragma unroll
        for (int nt = 0; nt < 4; nt++)
            #pragma unroll
            for (int q = 0; q < 4; q++) acc[mt][nt][q] = 0.f;

    gemm_mainloop(A, W, m0, n0, sb, acc, lane, wm, wn);

    #pragma unroll
    for (int mt = 0; mt < 4; mt++) {
        #pragma unroll
        for (int nt = 0; nt < 4; nt++) {
            #pragma unroll
            for (int q = 0; q < 4; q++) {
                const int m   = m0 + wm + mt * 16 + gid + 8 * (q >> 1);
                const int col = n0 + wn + nt * 8 + 2 * tig + (q & 1);
                const int h = col >> 6, d = col & 63;
                float val = acc[mt][nt][q];
                size_t idx;
                if (mode == 1) {
                    int b  = m >> 10, qq = m & 1023;
                    int t  = qq >> 4, g = qq & 7, rh = (qq >> 3) & 1;
                    int kk = d >> 4, hi = (d >> 3) & 1;
                    int tq = (d & 7) >> 1, ev = d & 1;
                    idx = ((((size_t)((b * 8 + h) * 64 + t) * 4 + kk) * 256)
                          + (g * 4 + tq) * 8 + (rh + 2 * hi) * 2 + ev);
                    val *= 0.125f;
                } else if (mode == 2) {
                    int b = m >> 11, n = m & 2047;
                    int kt = n >> 6, ri = n & 63;
                    int nt2 = ri >> 3, g = ri & 7;
                    int kk = d >> 4, hi = (d >> 3) & 1;
                    int t = (d & 7) >> 1, ev = d & 1;
                    idx = (size_t)((b * 32 + kt) * 8 + h) * 4096
                          + (kk * 8 + nt2) * 128 + (g * 4 + t) * 4
                          + hi * 2 + ev;
                } else {
                    int b = m >> 11, n = m & 2047;
                    int kt = n >> 6, kr = n & 63;
                    int kk = kr >> 4, hi = (kr >> 3) & 1;
                    int t = (kr & 7) >> 1, ev = kr & 1;
                    int nt2 = d >> 3, g = d & 7;
                    idx = (size_t)((b * 32 + kt) * 8 + h) * 4096
                          + (kk * 8 + nt2) * 128 + (g * 4 + t) * 4
                          + hi * 2 + ev;
                }
                C[idx] = __float2half_rn(val);
            }
        }
    }
}

// ---------------------------------------------------------------------------
// Output GEMM: out = g_AOh @ Wo^T + bo.  grid (8 n, 32 m).
// ---------------------------------------------------------------------------
__global__ __launch_bounds__(128, 4) void gemm_o_kernel(
    const float* __restrict__ bias, float* __restrict__ out)
{
    extern __shared__ __half smh[];
    const uint32_t sb = smem_u32(smh);

    const int tid  = threadIdx.x;
    const int w    = tid >> 5;
    const int lane = tid & 31;
    const int gid  = lane >> 2;
    const int tig  = lane & 3;
    const int wm   = (w >> 1) * 64;
    const int wn   = (w & 1) * 32;
    const int n0   = blockIdx.x * 64;
    const int m0   = blockIdx.y * 128;

    float acc[4][4][4];
    #pragma unroll
    for (int mt = 0; mt < 4; mt++)
        #pragma unroll
        for (int nt = 0; nt < 4; nt++)
            #pragma unroll
            for (int q = 0; q < 4; q++) acc[mt][nt][q] = 0.f;

    gemm_mainloop(g_AOh, g_Woh, m0, n0, sb, acc, lane, wm, wn);

    #pragma unroll
    for (int mt = 0; mt < 4; mt++) {
        const int r0 = m0 + wm + mt * 16 + gid;
        #pragma unroll
        for (int nt = 0; nt < 4; nt++) {
            const int col = n0 + wn + nt * 8 + 2 * tig;
            const float b0 = bias[col], b1 = bias[col + 1];
            *(float2*)(out + (size_t)r0 * DM + col) =
                make_float2(acc[mt][nt][0] + b0, acc[mt][nt][1] + b1);
            *(float2*)(out + (size_t)(r0 + 8) * DM + col) =
                make_float2(acc[mt][nt][2] + b0, acc[mt][nt][3] + b1);
        }
    }
}

// ===========================================================================
// Flash attention, fp16 mma, f32 accumulate, P in registers, SPLIT-KV x4.
// (uses cp_wait<0> — full drain, no tail hazard)
// ===========================================================================
#define ATTN_SMEM 49152
#define KV_SPLIT_TILES (32 / NSPLIT)

__global__ __launch_bounds__(128, 3) void attn_kernel(const float* __restrict__ bias)
{
    extern __shared__ __half smha[];
    const uint32_t sb = smem_u32(smha);

    const int tid   = threadIdx.x;
    const int w     = tid >> 5;
    const int lane  = tid & 31;
    const int gid   = lane >> 2;
    const int tig   = lane & 3;
    const int split = blockIdx.x & (NSPLIT - 1);
    const int qt    = blockIdx.x / NSPLIT;
    const int q0    = qt * 128;
    const int h     = blockIdx.y;
    const int b     = blockIdx.z;
    const int kb0   = split * KV_SPLIT_TILES;

    {
        const __half* gq = g_Qh + (size_t)((b * 8 + h) * 64 + qt * 8) * 1024;
        #pragma unroll
        for (int i = 0; i < 8; i++) {
            int off = i * 1024 + tid * 8;
            cp_async16(sb + (16384 + off) * 2, gq + off);
        }
    }
    {
        const __half* gk = g_Kh + ((size_t)(b * 32 + kb0) * 8 + h) * 4096;
        const __half* gv = g_Vh + ((size_t)(b * 32 + kb0) * 8 + h) * 4096;
        #pragma unroll
        for (int i = 0; i < 4; i++) {
            int off = i * 1024 + tid * 8;
            cp_async16(sb + ((kb0 & 1) * 4096 + off) * 2, gk + off);
            cp_async16(sb + (8192 + (kb0 & 1) * 4096 + off) * 2, gv + off);
        }
    }
    cp_commit();

    float o[2][8][4];
    #pragma unroll
    for (int mt = 0; mt < 2; mt++)
        #pragma unroll
        for (int nt = 0; nt < 8; nt++)
            #pragma unroll
            for (int q = 0; q < 4; q++) o[mt][nt][q] = 0.f;
    float mx[2][2] = {{-1e30f, -1e30f}, {-1e30f, -1e30f}};
    float ls[2][2] = {{0.f, 0.f}, {0.f, 0.f}};

    const int qbase = 16384 + w * 2048;

    for (int kb = kb0; kb < kb0 + KV_SPLIT_TILES; kb++) {
        cp_wait<0>();
        __syncthreads();

        if (kb + 1 < kb0 + KV_SPLIT_TILES) {
            const int nb = (kb + 1) & 1;
            const __half* gk = g_Kh + ((size_t)(b * 32 + kb + 1) * 8 + h) * 4096;
            const __half* gv = g_Vh + ((size_t)(b * 32 + kb + 1) * 8 + h) * 4096;
            #pragma unroll
            for (int i = 0; i < 4; i++) {
                int off = i * 1024 + tid * 8;
                cp_async16(sb + (nb * 4096 + off) * 2, gk + off);
                cp_async16(sb + (8192 + nb * 4096 + off) * 2, gv + off);
            }
            cp_commit();
        }

        const int kbo = (kb & 1) * 4096;

        float s[2][8][4];
        #pragma unroll
        for (int mt = 0; mt < 2; mt++)
            #pragma unroll
            for (int nt = 0; nt < 8; nt++)
                #pragma unroll
                for (int q = 0; q < 4; q++) s[mt][nt][q] = 0.f;

        #pragma unroll
        for (int kk = 0; kk < 4; kk++) {
            uint32_t af[2][4];
            #pragma unroll
            for (int mt = 0; mt < 2; mt++) {
                float4 a4 = *(const float4*)&smha[qbase + mt * 1024
                                                  + kk * 256 + lane * 8];
                af[mt][0] = __float_as_uint(a4.x); af[mt][1] = __float_as_uint(a4.y);
                af[mt][2] = __float_as_uint(a4.z); af[mt][3] = __float_as_uint(a4.w);
            }
            #pragma unroll
            for (int nt = 0; nt < 8; nt++) {
                uint2 k2 = *(const uint2*)&smha[kbo + (kk * 8 + nt) * 128 + lane * 4];
                mma_f16(s[0][nt], af[0], k2.x, k2.y);
                mma_f16(s[1][nt], af[1], k2.x, k2.y);
            }
        }

        #pragma unroll
        for (int mt = 0; mt < 2; mt++) {
            const float* bLo = bias
                + ((size_t)b * NQS + q0 + 32 * w + 16 * mt + gid) * NKS + kb * 64;
            const float* bHi = bLo + 8 * (size_t)NKS;

            float rmLo = -1e30f, rmHi = -1e30f;
            #pragma unroll
            for (int nt = 0; nt < 8; nt++) {
                float2 bl = *(const float2*)(bLo + nt * 8 + 2 * tig);
                float2 bh = *(const float2*)(bHi + nt * 8 + 2 * tig);
                s[mt][nt][0] += bl.x;  s[mt][nt][1] += bl.y;
                s[mt][nt][2] += bh.x;  s[mt][nt][3] += bh.y;
                rmLo = fmaxf(rmLo, fmaxf(s[mt][nt][0], s[mt][nt][1]));
                rmHi = fmaxf(rmHi, fmaxf(s[mt][nt][2], s[mt][nt][3]));
            }
            rmLo = fmaxf(rmLo, __shfl_xor_sync(0xffffffffu, rmLo, 1));
            rmLo = fmaxf(rmLo, __shfl_xor_sync(0xffffffffu, rmLo, 2));
            rmHi = fmaxf(rmHi, __shfl_xor_sync(0xffffffffu, rmHi, 1));
            rmHi = fmaxf(rmHi, __shfl_xor_sync(0xffffffffu, rmHi, 2));

            const float mnLo = fmaxf(mx[mt][0], rmLo);
            const float mnHi = fmaxf(mx[mt][1], rmHi);
            const float corrLo = __expf(mx[mt][0] - mnLo);
            const float corrHi = __expf(mx[mt][1] - mnHi);
            mx[mt][0] = mnLo; mx[mt][1] = mnHi;

            float rsLo = 0.f, rsHi = 0.f;
            #pragma unroll
            for (int nt = 0; nt < 8; nt++) {
                float p0 = __expf(s[mt][nt][0] - mnLo);
                float p1 = __expf(s[mt][nt][1] - mnLo);
                float p2 = __expf(s[mt][nt][2] - mnHi);
                float p3 = __expf(s[mt][nt][3] - mnHi);
                rsLo += p0 + p1;
                rsHi += p2 + p3;
                s[mt][nt][0] = p0; s[mt][nt][1] = p1;
                s[mt][nt][2] = p2; s[mt][nt][3] = p3;
                o[mt][nt][0] *= corrLo; o[mt][nt][1] *= corrLo;
                o[mt][nt][2] *= corrHi; o[mt][nt][3] *= corrHi;
            }
            rsLo += __shfl_xor_sync(0xffffffffu, rsLo, 1);
            rsLo += __shfl_xor_sync(0xffffffffu, rsLo, 2);
            rsHi += __shfl_xor_sync(0xffffffffu, rsHi, 1);
            rsHi += __shfl_xor_sync(0xffffffffu, rsHi, 2);
            ls[mt][0] = ls[mt][0] * corrLo + rsLo;
            ls[mt][1] = ls[mt][1] * corrHi + rsHi;
        }

        #pragma unroll
        for (int kk = 0; kk < 4; kk++) {
            uint32_t af[2][4];
            #pragma unroll
            for (int mt = 0; mt < 2; mt++) {
                af[mt][0] = h2u(s[mt][2 * kk][0],     s[mt][2 * kk][1]);
                af[mt][1] = h2u(s[mt][2 * kk][2],     s[mt][2 * kk][3]);
                af[mt][2] = h2u(s[mt][2 * kk + 1][0], s[mt][2 * kk + 1][1]);
                af[mt][3] = h2u(s[mt][2 * kk + 1][2], s[mt][2 * kk + 1][3]);
            }
            #pragma unroll
            for (int nt = 0; nt < 8; nt++) {
                uint2 v2 = *(const uint2*)&smha[8192 + kbo
                                                + (kk * 8 + nt) * 128 + lane * 4];
                mma_f16(o[0][nt], af[0], v2.x, v2.y);
                mma_f16(o[1][nt], af[1], v2.x, v2.y);
            }
        }
    }

    float* Opart = g_Part[split];
    #pragma unroll
    for (int mt = 0; mt < 2; mt++) {
        const int rowLo = q0 + 32 * w + 16 * mt + gid;
        float* OgLo = Opart + ((size_t)b * NQS + rowLo) * DM + h * DH;
        float* OgHi = OgLo + 8 * (size_t)DM;
        #pragma unroll
        for (int nt = 0; nt < 8; nt++) {
            int col = nt * 8 + 2 * tig;
            *(float2*)(OgLo + col) = make_float2(o[mt][nt][0], o[mt][nt][1]);
            *(float2*)(OgHi + col) = make_float2(o[mt][nt][2], o[mt][nt][3]);
        }
        if (tig == 0) {
            int mi = (b * 8 + h) * 1024 + rowLo;
            g_M[split][mi]     = mx[mt][0];
            g_L[split][mi]     = ls[mt][0];
            g_M[split][mi + 8] = mx[mt][1];
            g_L[split][mi + 8] = ls[mt][1];
        }
    }
}

// ===========================================================================
// Merge the NSPLIT KV splits; emit fp16 (A operand of output GEMM).
// ===========================================================================
__global__ __launch_bounds__(256) void merge_kernel()
{
    const size_t i = (size_t)blockIdx.x * 256 + threadIdx.x;   // per float2
    const size_t e = i * 2;
    const size_t row = e / DM;
    const int d  = (int)(e % DM);
    const int b  = (int)(row >> 10);
    const int q  = (int)(row & 1023);
    const int h  = d >> 6;
    const int mi = (b * 8 + h) * 1024 + q;

    float m[NSPLIT], l[NSPLIT];
    float ms = -1e30f;
    #pragma unroll
    for (int s = 0; s < NSPLIT; s++) {
        m[s] = g_M[s][mi];
        l[s] = g_L[s][mi];
        ms = fmaxf(ms, m[s]);
    }
    float den = 0.f;
    float a[NSPLIT];
    #pragma unroll
    for (int s = 0; s < NSPLIT; s++) {
        a[s] = __expf(m[s] - ms);
        den += l[s] * a[s];
    }
    const float inv = 1.f / den;

    float ox = 0.f, oy = 0.f;
    #pragma unroll
    for (int s = 0; s < NSPLIT; s++) {
        const float2 p = *(const float2*)&g_Part[s][e];
        ox += p.x * a[s];
        oy += p.y * a[s];
    }
    *(uint32_t*)&g_AOh[e] = h2u(ox * inv, oy * inv);
}

// ---------------------------------------------------------------------------
// Launch
// ---------------------------------------------------------------------------
extern "C" void kernel_launch(void* const* d_in, const int* in_sizes, int n_in,
                              void* d_out, int out_size)
{
    const float* x    = (const float*)d_in[0];
    const float* ctx  = (const float*)d_in[1];
    const float* bias = (const float*)d_in[2];
    const float* Wq   = (const float*)d_in[3];
    const float* Wk   = (const float*)d_in[4];
    const float* Wv   = (const float*)d_in[5];
    const float* Wo   = (const float*)d_in[6];
    const float* bo   = (const float*)d_in[7];
    float* out = (float*)d_out;

    cudaFuncSetAttribute(gemm_qkv_kernel,
                         cudaFuncAttributeMaxDynamicSharedMemorySize, GEMM_SMEM);
    cudaFuncSetAttribute(gemm_o_kernel,
                         cudaFuncAttributeMaxDynamicSharedMemorySize, GEMM_SMEM);
    cudaFuncSetAttribute(attn_kernel,
                         cudaFuncAttributeMaxDynamicSharedMemorySize, ATTN_SMEM);

    conv_all_kernel<<<CONV_BLOCKS, 256>>>(x, ctx, Wq, Wk, Wv, Wo);
    gemm_qkv_kernel<<<1280, 128, GEMM_SMEM>>>();
    attn_kernel<<<dim3((NQS / 128) * NSPLIT, NHEADS, BATCH),
                  dim3(128), ATTN_SMEM>>>(bias);
    merge_kernel<<<(BATCH * NQS * DM / 2) / 256, 256>>>();
    gemm_o_kernel<<<dim3(8, 32), 128, GEMM_SMEM>>>(bo, out);
}